// round 8
// baseline (speedup 1.0000x reference)
#include <cuda_runtime.h>
#include <math.h>
#include <stdint.h>

// ---------------------------------------------------------------------------
// Problem constants
// ---------------------------------------------------------------------------
#define B_   4
#define N_   2048
#define D_   768
#define H_   12
#define HD_  64
#define M_   (B_ * N_)             // 8192
#define QKV_COLS (3 * D_)          // 2304

// Scratch (alloc-free rule)
__device__ float g_qkv[(size_t)M_ * QKV_COLS];
__device__ float g_att[(size_t)M_ * D_];
__device__ float g_wqkvT[(size_t)QKV_COLS * D_];   // [N=2304][K=768]
__device__ float g_wprojT[(size_t)D_ * D_];        // [N=768][K=768]

// ---------------------------------------------------------------------------
// tf32 helpers (legacy mma path — harness targets sm_100 base, no tcgen05)
// ---------------------------------------------------------------------------
__device__ __forceinline__ uint32_t f2tf(float x) {
    uint32_t r;
    asm("cvt.rna.tf32.f32 %0, %1;" : "=r"(r) : "f"(x));
    return r;
}

__device__ __forceinline__ float tff(float x) {   // tf32 round, keep as float bits
    float r;
    asm("{ .reg .b32 t; cvt.rna.tf32.f32 t, %1; mov.b32 %0, t; }" : "=f"(r) : "f"(x));
    return r;
}

__device__ __forceinline__ float ex2(float x) {
    float y;
    asm("ex2.approx.ftz.f32 %0, %1;" : "=f"(y) : "f"(x));
    return y;
}

__device__ __forceinline__ void mma_tf32(float* c, const uint32_t* a, const uint32_t* b) {
    asm volatile(
        "mma.sync.aligned.m16n8k8.row.col.f32.tf32.tf32.f32 "
        "{%0,%1,%2,%3}, {%4,%5,%6,%7}, {%8,%9}, {%0,%1,%2,%3};"
        : "+f"(c[0]), "+f"(c[1]), "+f"(c[2]), "+f"(c[3])
        : "r"(a[0]), "r"(a[1]), "r"(a[2]), "r"(a[3]), "r"(b[0]), "r"(b[1]));
}

// ---------------------------------------------------------------------------
// Weight transpose: out[N][K] = in[K][N]
// ---------------------------------------------------------------------------
__global__ __launch_bounds__(256) void transpose_k(
    const float* __restrict__ in, float* __restrict__ out, int K, int N)
{
    __shared__ float t[32][33];
    const int kb = blockIdx.y * 32, nb = blockIdx.x * 32;
    const int x = threadIdx.x, y = threadIdx.y;
    #pragma unroll
    for (int i = 0; i < 32; i += 8)
        t[y + i][x] = in[(size_t)(kb + y + i) * N + nb + x];
    __syncthreads();
    #pragma unroll
    for (int i = 0; i < 32; i += 8)
        out[(size_t)(nb + y + i) * K + kb + x] = t[x][y + i];
}

// ---------------------------------------------------------------------------
// tf32 GEMM, fragment-major smem + 2-stage pipeline (unchanged from R7 win).
// ---------------------------------------------------------------------------
#define FF_SMEM (16512 * 4)

template<bool BIAS>
__global__ __launch_bounds__(256, 2) void gemm_ff(
    const float* __restrict__ A, const float* __restrict__ WT,
    const float* __restrict__ bias, float* __restrict__ C,
    int N, int K)
{
    extern __shared__ float smf[];

    const int tid  = threadIdx.x;
    const int lane = tid & 31;
    const int wid  = tid >> 5;
    const int g    = lane >> 2;
    const int tg   = lane & 3;
    const int wm   = wid & 3;
    const int wn   = wid >> 2;
    const int row0 = blockIdx.y * 128;
    const int col0 = blockIdx.x * 128;
    const int KT   = K / 32;

    float acc[2][8][4];
    #pragma unroll
    for (int mt = 0; mt < 2; mt++)
        #pragma unroll
        for (int nt = 0; nt < 8; nt++)
            #pragma unroll
            for (int i = 0; i < 4; i++) acc[mt][nt][i] = 0.f;

    const int lrow = tid >> 3;
    const int lkq  = tid & 7;
    const int ks0  = lkq >> 1;
    const int m0   = lkq & 1;
    const int kA   = 8 * ks0 + 2 * m0;

    const float* Ap = A  + (size_t)(row0 + lrow) * K + kA;
    const float* Bp = WT + (size_t)(col0 + lrow) * K + kA;

    float2 rg[2][4][2];

    #define LOAD_TILE(t_) do {                                               \
        const size_t koff_ = (size_t)(t_) * 32;                             \
        _Pragma("unroll")                                                    \
        for (int i_ = 0; i_ < 4; i_++) {                                     \
            const float* a_ = Ap + (size_t)(i_ * 32) * K + koff_;            \
            const float* b_ = Bp + (size_t)(i_ * 32) * K + koff_;            \
            rg[0][i_][0] = *(const float2*)a_;                               \
            rg[0][i_][1] = *(const float2*)(a_ + 4);                         \
            rg[1][i_][0] = *(const float2*)b_;                               \
            rg[1][i_][1] = *(const float2*)(b_ + 4);                         \
        }                                                                    \
    } while (0)

    #define STORE_TILE(s_) do {                                              \
        float* baseA_ = smf + (s_) * 8256 + ks0 * 1032 + 4 * m0;             \
        float* baseB_ = baseA_ + 4128;                                       \
        _Pragma("unroll")                                                    \
        for (int i_ = 0; i_ < 4; i_++) {                                     \
            const int r_ = lrow + 32 * i_;                                   \
            uint4 pa_ = make_uint4(f2tf(rg[0][i_][0].x), f2tf(rg[0][i_][1].x),\
                                   f2tf(rg[0][i_][0].y), f2tf(rg[0][i_][1].y));\
            uint4 pb_ = make_uint4(f2tf(rg[1][i_][0].x), f2tf(rg[1][i_][1].x),\
                                   f2tf(rg[1][i_][0].y), f2tf(rg[1][i_][1].y));\
            *(uint4*)(baseA_ + r_ * 8) = pa_;                                \
            *(uint4*)(baseB_ + r_ * 8) = pb_;                                \
        }                                                                    \
    } while (0)

    LOAD_TILE(0);
    STORE_TILE(0);
    if (KT > 1) LOAD_TILE(1);
    __syncthreads();

    for (int t = 0; t < KT; t++) {
        const int s = t & 1;

        if (t + 1 < KT) {
            STORE_TILE(s ^ 1);
            if (t + 2 < KT) LOAD_TILE(t + 2);
        }

        const float2* As2 = (const float2*)(smf + s * 8256);
        const float2* Bs2 = (const float2*)(smf + s * 8256 + 4128);

        #pragma unroll
        for (int ks = 0; ks < 4; ks++) {
            const float2* Ak = As2 + ks * 516;
            const float2* Bk = Bs2 + ks * 516;
            uint32_t af[2][4];
            #pragma unroll
            for (int mt = 0; mt < 2; mt++) {
                const int r = wm * 32 + mt * 16 + g;
                float2 v1 = Ak[r * 4 + tg];
                float2 v2 = Ak[(r + 8) * 4 + tg];
                af[mt][0] = __float_as_uint(v1.x);
                af[mt][1] = __float_as_uint(v2.x);
                af[mt][2] = __float_as_uint(v1.y);
                af[mt][3] = __float_as_uint(v2.y);
            }
            #pragma unroll
            for (int nt = 0; nt < 8; nt++) {
                const int c = wn * 64 + nt * 8 + g;
                float2 w = Bk[c * 4 + tg];
                uint32_t bf[2] = { __float_as_uint(w.x), __float_as_uint(w.y) };
                mma_tf32(acc[0][nt], af[0], bf);
                mma_tf32(acc[1][nt], af[1], bf);
            }
        }
        __syncthreads();
    }

    #undef LOAD_TILE
    #undef STORE_TILE

    #pragma unroll
    for (int mt = 0; mt < 2; mt++) {
        const int r_lo = row0 + wm * 32 + mt * 16 + g;
        const int r_hi = r_lo + 8;
        #pragma unroll
        for (int nt = 0; nt < 8; nt++) {
            const int c = col0 + wn * 64 + nt * 8 + 2 * tg;
            float2 v0 = make_float2(acc[mt][nt][0], acc[mt][nt][1]);
            float2 v1 = make_float2(acc[mt][nt][2], acc[mt][nt][3]);
            if (BIAS) {
                float2 bb = *(const float2*)&bias[c];
                v0.x += bb.x; v0.y += bb.y;
                v1.x += bb.x; v1.y += bb.y;
            }
            *(float2*)&C[(size_t)r_lo * N + c] = v0;
            *(float2*)&C[(size_t)r_hi * N + c] = v1;
        }
    }
}

// ---------------------------------------------------------------------------
// Flash attention, tf32 mma, fragment-major Q/K/P smem (LDS.64 fragments).
//
// Layouts (words):
//   Qs/Ps: plane ks (0..7) stride QPL=1032; word(r,tg,slot)=ks*QPL+r*8+tg*2+slot
//          pair = { X[r][8ks+tg], X[r][8ks+tg+4] }
//   Kr:    plane ks stride KPL=520;  word(j,tg,slot)=ks*KPL+j*8+tg*2+slot
//   Vs:    row-major [j][d], LDVV=72 (unchanged)
// All mma fragment reads = LDS.64, conflict-free (banks 8g+2tg tile evens).
// Q pre-scaled by 0.125*log2(e); softmax in log2 domain via ex2.approx.
// ---------------------------------------------------------------------------
#define QPL 1032
#define KPL 520
#define LDVV 72
#define QROWS 128
#define AT_SMEM ((8 * QPL * 2 + 8 * KPL + 64 * LDVV) * 4)   // 101120 B

__global__ __launch_bounds__(256) void attn_tc(
    const float* __restrict__ qkv, float* __restrict__ out)
{
    extern __shared__ float sm[];
    float* Qs = sm;                         // 8*QPL
    float* Ps = sm + 8 * QPL;               // 8*QPL
    float* Kr = sm + 16 * QPL;              // 8*KPL
    float* Vs = sm + 16 * QPL + 8 * KPL;    // 64*LDVV

    const int tid  = threadIdx.x;
    const int lane = tid & 31;
    const int wid  = tid >> 5;
    const int g    = lane >> 2;
    const int tg   = lane & 3;
    const int qb   = blockIdx.x;            // 0..15
    const int bh   = blockIdx.y;            // 0..47
    const int b    = bh / H_;
    const int h    = bh % H_;

    const size_t base = (size_t)b * N_ * QKV_COLS;
    const int qoff = h * HD_;
    const int koff = D_ + h * HD_;
    const int voff = 2 * D_ + h * HD_;

    // loader mapping
    const int lr0 = tid >> 4;                // 0..15
    const int lq  = tid & 15;
    const int ks0 = lq >> 1;                 // 0..7
    const int m0  = lq & 1;
    const int d0  = 8 * ks0 + 2 * m0;        // K/Q pair column base
    const int ld  = lq * 4;                  // V column base

    const float QSC = 0.18033688011112042f;  // 0.125 * log2(e)

    // ---- stage Q (fragment-major, pre-scaled) ----
    #pragma unroll
    for (int i = 0; i < 8; i++) {
        const int r = lr0 + 16 * i;
        const float* qrow = &qkv[base + (size_t)(qb * QROWS + r) * QKV_COLS + qoff];
        float2 a = *(const float2*)(qrow + d0);
        float2 c = *(const float2*)(qrow + d0 + 4);
        uint4 u = make_uint4(f2tf(a.x * QSC), f2tf(c.x * QSC),
                             f2tf(a.y * QSC), f2tf(c.y * QSC));
        *(uint4*)&Qs[ks0 * QPL + r * 8 + 4 * m0] = u;
    }

    // ---- prefetch K/V tile 0 ----
    float2 k0[4], k1[4];
    float4 pv[4];
    #pragma unroll
    for (int i = 0; i < 4; i++) {
        const size_t grow = base + (size_t)(lr0 + i * 16) * QKV_COLS;
        k0[i] = *(const float2*)&qkv[grow + koff + d0];
        k1[i] = *(const float2*)&qkv[grow + koff + d0 + 4];
        pv[i] = *(const float4*)&qkv[grow + voff + ld];
    }
    __syncthreads();

    const int r_lo = wid * 16 + g;
    const int r_hi = r_lo + 8;

    // P-store word offsets (element d -> (d&3)*2 + (d>>2))
    const int dd0 = 2 * tg, dd1 = 2 * tg + 1;
    const int poff0 = (dd0 & 3) * 2 + (dd0 >> 2);
    const int poff1 = (dd1 & 3) * 2 + (dd1 >> 2);

    float O[8][4];
    #pragma unroll
    for (int nt = 0; nt < 8; nt++)
        #pragma unroll
        for (int i = 0; i < 4; i++) O[nt][i] = 0.f;
    float m_lo = -INFINITY, m_hi = -INFINITY, l_lo = 0.f, l_hi = 0.f;

    for (int t = 0; t < N_ / 64; t++) {
        // ---- stage K (fragment-major) + V (row-major) ----
        #pragma unroll
        for (int i = 0; i < 4; i++) {
            const int j = lr0 + 16 * i;
            *(uint4*)&Kr[ks0 * KPL + j * 8 + 4 * m0] =
                make_uint4(f2tf(k0[i].x), f2tf(k1[i].x), f2tf(k0[i].y), f2tf(k1[i].y));
            *(uint4*)&Vs[j * LDVV + ld] =
                make_uint4(f2tf(pv[i].x), f2tf(pv[i].y), f2tf(pv[i].z), f2tf(pv[i].w));
        }
        __syncthreads();

        // prefetch next tile (overlaps mma)
        if (t + 1 < N_ / 64) {
            #pragma unroll
            for (int i = 0; i < 4; i++) {
                const size_t grow = base + (size_t)((t + 1) * 64 + lr0 + i * 16) * QKV_COLS;
                k0[i] = *(const float2*)&qkv[grow + koff + d0];
                k1[i] = *(const float2*)&qkv[grow + koff + d0 + 4];
                pv[i] = *(const float4*)&qkv[grow + voff + ld];
            }
        }

        // ---- S = Q @ K^T (log2-scaled) ----
        float s[8][4];
        #pragma unroll
        for (int nt = 0; nt < 8; nt++)
            #pragma unroll
            for (int i = 0; i < 4; i++) s[nt][i] = 0.f;

        #pragma unroll
        for (int ks = 0; ks < 8; ks++) {
            uint32_t qf[4];
            {
                float2 t0 = *(const float2*)&Qs[ks * QPL + r_lo * 8 + tg * 2];
                float2 t1 = *(const float2*)&Qs[ks * QPL + r_hi * 8 + tg * 2];
                qf[0] = __float_as_uint(t0.x); qf[2] = __float_as_uint(t0.y);
                qf[1] = __float_as_uint(t1.x); qf[3] = __float_as_uint(t1.y);
            }
            const float* Kp = &Kr[ks * KPL];
            #pragma unroll
            for (int nt = 0; nt < 8; nt++) {
                float2 w = *(const float2*)&Kp[(nt * 8 + g) * 8 + tg * 2];
                uint32_t bf[2] = { __float_as_uint(w.x), __float_as_uint(w.y) };
                mma_tf32(s[nt], qf, bf);
            }
        }

        // ---- online softmax (log2 domain, ex2.approx) ----
        float rmx_lo = -INFINITY, rmx_hi = -INFINITY;
        #pragma unroll
        for (int nt = 0; nt < 8; nt++) {
            rmx_lo = fmaxf(rmx_lo, fmaxf(s[nt][0], s[nt][1]));
            rmx_hi = fmaxf(rmx_hi, fmaxf(s[nt][2], s[nt][3]));
        }
        rmx_lo = fmaxf(rmx_lo, __shfl_xor_sync(0xffffffffu, rmx_lo, 1));
        rmx_lo = fmaxf(rmx_lo, __shfl_xor_sync(0xffffffffu, rmx_lo, 2));
        rmx_hi = fmaxf(rmx_hi, __shfl_xor_sync(0xffffffffu, rmx_hi, 1));
        rmx_hi = fmaxf(rmx_hi, __shfl_xor_sync(0xffffffffu, rmx_hi, 2));

        const float mn_lo = fmaxf(m_lo, rmx_lo);
        const float mn_hi = fmaxf(m_hi, rmx_hi);
        const float sc_lo = ex2(m_lo - mn_lo);
        const float sc_hi = ex2(m_hi - mn_hi);

        float rs_lo = 0.f, rs_hi = 0.f;
        #pragma unroll
        for (int nt = 0; nt < 8; nt++) {
            s[nt][0] = ex2(s[nt][0] - mn_lo);
            s[nt][1] = ex2(s[nt][1] - mn_lo);
            s[nt][2] = ex2(s[nt][2] - mn_hi);
            s[nt][3] = ex2(s[nt][3] - mn_hi);
            rs_lo += s[nt][0] + s[nt][1];
            rs_hi += s[nt][2] + s[nt][3];
        }
        rs_lo += __shfl_xor_sync(0xffffffffu, rs_lo, 1);
        rs_lo += __shfl_xor_sync(0xffffffffu, rs_lo, 2);
        rs_hi += __shfl_xor_sync(0xffffffffu, rs_hi, 1);
        rs_hi += __shfl_xor_sync(0xffffffffu, rs_hi, 2);

        l_lo = l_lo * sc_lo + rs_lo;   m_lo = mn_lo;
        l_hi = l_hi * sc_hi + rs_hi;   m_hi = mn_hi;

        #pragma unroll
        for (int nt = 0; nt < 8; nt++) {
            O[nt][0] *= sc_lo; O[nt][1] *= sc_lo;
            O[nt][2] *= sc_hi; O[nt][3] *= sc_hi;
        }

        // ---- store P (fragment-major, warp-private rows) ----
        #pragma unroll
        for (int nt = 0; nt < 8; nt++) {
            float* Pp = &Ps[nt * QPL];
            Pp[r_lo * 8 + poff0] = tff(s[nt][0]);
            Pp[r_lo * 8 + poff1] = tff(s[nt][1]);
            Pp[r_hi * 8 + poff0] = tff(s[nt][2]);
            Pp[r_hi * 8 + poff1] = tff(s[nt][3]);
        }
        __syncwarp();

        // ---- O += P @ V ----
        #pragma unroll
        for (int ks = 0; ks < 8; ks++) {
            uint32_t pa[4];
            {
                float2 t0 = *(const float2*)&Ps[ks * QPL + r_lo * 8 + tg * 2];
                float2 t1 = *(const float2*)&Ps[ks * QPL + r_hi * 8 + tg * 2];
                pa[0] = __float_as_uint(t0.x); pa[2] = __float_as_uint(t0.y);
                pa[1] = __float_as_uint(t1.x); pa[3] = __float_as_uint(t1.y);
            }
            const float* Vp = &Vs[(ks * 8 + tg) * LDVV];
            const float* Vp4 = Vp + 4 * LDVV;
            #pragma unroll
            for (int nt = 0; nt < 8; nt++) {
                uint32_t bv[2] = { __float_as_uint(Vp[nt * 8 + g]),
                                   __float_as_uint(Vp4[nt * 8 + g]) };
                mma_tf32(O[nt], pa, bv);
            }
        }
        __syncthreads();   // guard Kr/Vs overwrite next iter
    }

    // ---- finalize + write [B,N,D] ----
    const float il_lo = 1.f / l_lo;
    const float il_hi = 1.f / l_hi;
    const int n_lo = qb * QROWS + r_lo;
    const int n_hi = n_lo + 8;
    #pragma unroll
    for (int nt = 0; nt < 8; nt++) {
        const int c = h * HD_ + nt * 8 + 2 * tg;
        float2 vlo = make_float2(O[nt][0] * il_lo, O[nt][1] * il_lo);
        float2 vhi = make_float2(O[nt][2] * il_hi, O[nt][3] * il_hi);
        *(float2*)&out[((size_t)b * N_ + n_lo) * D_ + c] = vlo;
        *(float2*)&out[((size_t)b * N_ + n_hi) * D_ + c] = vhi;
    }
}

// ---------------------------------------------------------------------------
// Launch
// ---------------------------------------------------------------------------
extern "C" void kernel_launch(void* const* d_in, const int* in_sizes, int n_in,
                              void* d_out, int out_size)
{
    const float* x      = (const float*)d_in[0];
    const float* w_qkv  = (const float*)d_in[1];
    const float* w_proj = (const float*)d_in[2];
    const float* b_proj = (const float*)d_in[3];
    float* out = (float*)d_out;

    float *qkv, *att, *wqkvT, *wprojT;
    cudaGetSymbolAddress((void**)&qkv, g_qkv);
    cudaGetSymbolAddress((void**)&att, g_att);
    cudaGetSymbolAddress((void**)&wqkvT, g_wqkvT);
    cudaGetSymbolAddress((void**)&wprojT, g_wprojT);

    cudaFuncSetAttribute(attn_tc, cudaFuncAttributeMaxDynamicSharedMemorySize, AT_SMEM);
    cudaFuncSetAttribute(gemm_ff<false>, cudaFuncAttributeMaxDynamicSharedMemorySize, FF_SMEM);
    cudaFuncSetAttribute(gemm_ff<true>,  cudaFuncAttributeMaxDynamicSharedMemorySize, FF_SMEM);

    // 0) transpose weights to K-major
    transpose_k<<<dim3(QKV_COLS / 32, D_ / 32), dim3(32, 8)>>>(w_qkv, wqkvT, D_, QKV_COLS);
    transpose_k<<<dim3(D_ / 32, D_ / 32), dim3(32, 8)>>>(w_proj, wprojT, D_, D_);

    // 1) QKV = X @ W_qkv
    gemm_ff<false><<<dim3(QKV_COLS / 128, M_ / 128), 256, FF_SMEM>>>(
        x, wqkvT, nullptr, qkv, QKV_COLS, D_);

    // 2) fused flash attention -> [B,N,D]
    attn_tc<<<dim3(N_ / QROWS, B_ * H_), 256, AT_SMEM>>>(qkv, att);

    // 3) OUT = ATT @ W_proj + b
    gemm_ff<true><<<dim3(D_ / 128, M_ / 128), 256, FF_SMEM>>>(
        att, wprojT, b_proj, out, D_, D_);
}

// round 9
// speedup vs baseline: 1.1420x; 1.1420x over previous
#include <cuda_runtime.h>
#include <math.h>
#include <stdint.h>

// ---------------------------------------------------------------------------
// Problem constants
// ---------------------------------------------------------------------------
#define B_   4
#define N_   2048
#define D_   768
#define H_   12
#define HD_  64
#define M_   (B_ * N_)             // 8192
#define QKV_COLS (3 * D_)          // 2304

// Scratch (alloc-free rule)
__device__ float g_qkv[(size_t)M_ * QKV_COLS];
__device__ float g_att[(size_t)M_ * D_];
__device__ float g_wqkvT[(size_t)QKV_COLS * D_];   // [N=2304][K=768]
__device__ float g_wprojT[(size_t)D_ * D_];        // [N=768][K=768]

// ---------------------------------------------------------------------------
// tf32 helpers (legacy mma path — harness targets sm_100 base, no tcgen05)
// ---------------------------------------------------------------------------
__device__ __forceinline__ uint32_t f2tf(float x) {
    uint32_t r;
    asm("cvt.rna.tf32.f32 %0, %1;" : "=r"(r) : "f"(x));
    return r;
}

__device__ __forceinline__ float tff(float x) {   // tf32 round, keep float
    float r;
    asm("{ .reg .b32 t; cvt.rna.tf32.f32 t, %1; mov.b32 %0, t; }" : "=f"(r) : "f"(x));
    return r;
}

__device__ __forceinline__ float ex2(float x) {
    float y;
    asm("ex2.approx.ftz.f32 %0, %1;" : "=f"(y) : "f"(x));
    return y;
}

__device__ __forceinline__ void mma_tf32(float* c, const uint32_t* a, const uint32_t* b) {
    asm volatile(
        "mma.sync.aligned.m16n8k8.row.col.f32.tf32.tf32.f32 "
        "{%0,%1,%2,%3}, {%4,%5,%6,%7}, {%8,%9}, {%0,%1,%2,%3};"
        : "+f"(c[0]), "+f"(c[1]), "+f"(c[2]), "+f"(c[3])
        : "r"(a[0]), "r"(a[1]), "r"(a[2]), "r"(a[3]), "r"(b[0]), "r"(b[1]));
}

__device__ __forceinline__ void cpa16(uint32_t dst, const float* src) {
    asm volatile("cp.async.ca.shared.global [%0], [%1], 16;"
                 :: "r"(dst), "l"(src) : "memory");
}
__device__ __forceinline__ void cpa_commit() {
    asm volatile("cp.async.commit_group;" ::: "memory");
}
template<int NN>
__device__ __forceinline__ void cpa_wait() {
    asm volatile("cp.async.wait_group %0;" :: "n"(NN) : "memory");
}

__device__ __forceinline__ uint32_t smem_u32(const void* p) {
    uint32_t a;
    asm("{ .reg .u64 t; cvta.to.shared.u64 t, %1; cvt.u32.u64 %0, t; }" : "=r"(a) : "l"(p));
    return a;
}

// ---------------------------------------------------------------------------
// Weight transpose: out[N][K] = in[K][N]; optionally scale first qrows rows.
// ---------------------------------------------------------------------------
__global__ __launch_bounds__(256) void transpose_k(
    const float* __restrict__ in, float* __restrict__ out, int K, int N,
    int qrows, float qscale)
{
    __shared__ float t[32][33];
    const int kb = blockIdx.y * 32, nb = blockIdx.x * 32;
    const int x = threadIdx.x, y = threadIdx.y;
    #pragma unroll
    for (int i = 0; i < 32; i += 8)
        t[y + i][x] = in[(size_t)(kb + y + i) * N + nb + x];
    __syncthreads();
    #pragma unroll
    for (int i = 0; i < 32; i += 8) {
        const int n = nb + y + i;
        const float s = (n < qrows) ? qscale : 1.0f;
        out[(size_t)n * K + kb + x] = t[x][y + i] * s;
    }
}

// ---------------------------------------------------------------------------
// tf32 GEMM, fragment-major smem + 2-stage pipeline (R7 win), with optional
// tf32-rounded output (so downstream consumers can use raw values).
// ---------------------------------------------------------------------------
#define FF_SMEM (16512 * 4)

template<bool BIAS, bool ROUND>
__global__ __launch_bounds__(256, 2) void gemm_ff(
    const float* __restrict__ A, const float* __restrict__ WT,
    const float* __restrict__ bias, float* __restrict__ C,
    int N, int K)
{
    extern __shared__ float smf[];

    const int tid  = threadIdx.x;
    const int lane = tid & 31;
    const int wid  = tid >> 5;
    const int g    = lane >> 2;
    const int tg   = lane & 3;
    const int wm   = wid & 3;
    const int wn   = wid >> 2;
    const int row0 = blockIdx.y * 128;
    const int col0 = blockIdx.x * 128;
    const int KT   = K / 32;

    float acc[2][8][4];
    #pragma unroll
    for (int mt = 0; mt < 2; mt++)
        #pragma unroll
        for (int nt = 0; nt < 8; nt++)
            #pragma unroll
            for (int i = 0; i < 4; i++) acc[mt][nt][i] = 0.f;

    const int lrow = tid >> 3;
    const int lkq  = tid & 7;
    const int ks0  = lkq >> 1;
    const int m0   = lkq & 1;
    const int kA   = 8 * ks0 + 2 * m0;

    const float* Ap = A  + (size_t)(row0 + lrow) * K + kA;
    const float* Bp = WT + (size_t)(col0 + lrow) * K + kA;

    float2 rg[2][4][2];

    #define LOAD_TILE(t_) do {                                               \
        const size_t koff_ = (size_t)(t_) * 32;                             \
        _Pragma("unroll")                                                    \
        for (int i_ = 0; i_ < 4; i_++) {                                     \
            const float* a_ = Ap + (size_t)(i_ * 32) * K + koff_;            \
            const float* b_ = Bp + (size_t)(i_ * 32) * K + koff_;            \
            rg[0][i_][0] = *(const float2*)a_;                               \
            rg[0][i_][1] = *(const float2*)(a_ + 4);                         \
            rg[1][i_][0] = *(const float2*)b_;                               \
            rg[1][i_][1] = *(const float2*)(b_ + 4);                         \
        }                                                                    \
    } while (0)

    #define STORE_TILE(s_) do {                                              \
        float* baseA_ = smf + (s_) * 8256 + ks0 * 1032 + 4 * m0;             \
        float* baseB_ = baseA_ + 4128;                                       \
        _Pragma("unroll")                                                    \
        for (int i_ = 0; i_ < 4; i_++) {                                     \
            const int r_ = lrow + 32 * i_;                                   \
            uint4 pa_ = make_uint4(f2tf(rg[0][i_][0].x), f2tf(rg[0][i_][1].x),\
                                   f2tf(rg[0][i_][0].y), f2tf(rg[0][i_][1].y));\
            uint4 pb_ = make_uint4(f2tf(rg[1][i_][0].x), f2tf(rg[1][i_][1].x),\
                                   f2tf(rg[1][i_][0].y), f2tf(rg[1][i_][1].y));\
            *(uint4*)(baseA_ + r_ * 8) = pa_;                                \
            *(uint4*)(baseB_ + r_ * 8) = pb_;                                \
        }                                                                    \
    } while (0)

    LOAD_TILE(0);
    STORE_TILE(0);
    if (KT > 1) LOAD_TILE(1);
    __syncthreads();

    for (int t = 0; t < KT; t++) {
        const int s = t & 1;

        if (t + 1 < KT) {
            STORE_TILE(s ^ 1);
            if (t + 2 < KT) LOAD_TILE(t + 2);
        }

        const float2* As2 = (const float2*)(smf + s * 8256);
        const float2* Bs2 = (const float2*)(smf + s * 8256 + 4128);

        #pragma unroll
        for (int ks = 0; ks < 4; ks++) {
            const float2* Ak = As2 + ks * 516;
            const float2* Bk = Bs2 + ks * 516;
            uint32_t af[2][4];
            #pragma unroll
            for (int mt = 0; mt < 2; mt++) {
                const int r = wm * 32 + mt * 16 + g;
                float2 v1 = Ak[r * 4 + tg];
                float2 v2 = Ak[(r + 8) * 4 + tg];
                af[mt][0] = __float_as_uint(v1.x);
                af[mt][1] = __float_as_uint(v2.x);
                af[mt][2] = __float_as_uint(v1.y);
                af[mt][3] = __float_as_uint(v2.y);
            }
            #pragma unroll
            for (int nt = 0; nt < 8; nt++) {
                const int c = wn * 64 + nt * 8 + g;
                float2 w = Bk[c * 4 + tg];
                uint32_t bf[2] = { __float_as_uint(w.x), __float_as_uint(w.y) };
                mma_tf32(acc[0][nt], af[0], bf);
                mma_tf32(acc[1][nt], af[1], bf);
            }
        }
        __syncthreads();
    }

    #undef LOAD_TILE
    #undef STORE_TILE

    #pragma unroll
    for (int mt = 0; mt < 2; mt++) {
        const int r_lo = row0 + wm * 32 + mt * 16 + g;
        const int r_hi = r_lo + 8;
        #pragma unroll
        for (int nt = 0; nt < 8; nt++) {
            const int c = col0 + wn * 64 + nt * 8 + 2 * tg;
            float2 v0 = make_float2(acc[mt][nt][0], acc[mt][nt][1]);
            float2 v1 = make_float2(acc[mt][nt][2], acc[mt][nt][3]);
            if (BIAS) {
                float2 bb = *(const float2*)&bias[c];
                v0.x += bb.x; v0.y += bb.y;
                v1.x += bb.x; v1.y += bb.y;
            }
            if (ROUND) {
                v0.x = tff(v0.x); v0.y = tff(v0.y);
                v1.x = tff(v1.x); v1.y = tff(v1.y);
            }
            *(float2*)&C[(size_t)r_lo * N + c] = v0;
            *(float2*)&C[(size_t)r_hi * N + c] = v1;
        }
    }
}

// ---------------------------------------------------------------------------
// Flash attention, tf32 mma, cp.async 3-stage KV ring, Q fragments in regs.
// Inputs in g_qkv are already tf32-rounded; Q part pre-scaled by 0.125*log2e.
// Block: 128 q-rows of one (b,h), 256 threads (8 warps x 16 rows).
// KV tile = 32 rows; 64 iterations; one __syncthreads per iteration.
//
// smem (words):
//   Ps: 4 planes x 1032           @ 0      (fragment-major P)
//   K stages: 3 x (32x68)=2176    @ 4128   (row-major, LD=68)
//   V stages: 3 x (32x72)=2304    @ 10656  (row-major, LD=72)
// ---------------------------------------------------------------------------
#define QPL   1032
#define PS_OFF 0
#define KS_OFF 4128
#define KS_STRIDE 2176
#define VS_OFF 10656
#define VS_STRIDE 2304
#define LDK_  68
#define LDV_  72
#define QROWS 128
#define NTILES (N_ / 32)
#define AT_SMEM ((VS_OFF + 3 * VS_STRIDE) * 4)   // 70272 B

__global__ __launch_bounds__(256, 2) void attn_tc(
    const float* __restrict__ qkv, float* __restrict__ out)
{
    extern __shared__ float sm[];
    const uint32_t sb4 = smem_u32(sm);

    const int tid  = threadIdx.x;
    const int lane = tid & 31;
    const int wid  = tid >> 5;
    const int g    = lane >> 2;
    const int tg   = lane & 3;
    const int qb   = blockIdx.x;            // 0..15
    const int bh   = blockIdx.y;            // 0..47
    const int b    = bh / H_;
    const int h    = bh % H_;

    const size_t base = (size_t)b * N_ * QKV_COLS;
    const int qoff = h * HD_;
    const int koff = D_ + h * HD_;
    const int voff = 2 * D_ + h * HD_;

    // cp.async loader mapping: rows cr0, cr0+16; 16B chunk at col cd
    const int cr0 = tid >> 4;                // 0..15
    const int cd  = (tid & 15) * 4;          // 0..60

    #define ISSUE_TILE(tt_, ss_) do {                                        \
        const float* r0_ = qkv + base + (size_t)((tt_) * 32 + cr0) * QKV_COLS;\
        const float* r1_ = r0_ + (size_t)16 * QKV_COLS;                      \
        const uint32_t kd_ = sb4 + (KS_OFF + (ss_) * KS_STRIDE) * 4;         \
        const uint32_t vd_ = sb4 + (VS_OFF + (ss_) * VS_STRIDE) * 4;         \
        cpa16(kd_ + (cr0 * LDK_ + cd) * 4,        r0_ + koff + cd);          \
        cpa16(kd_ + ((cr0 + 16) * LDK_ + cd) * 4, r1_ + koff + cd);          \
        cpa16(vd_ + (cr0 * LDV_ + cd) * 4,        r0_ + voff + cd);          \
        cpa16(vd_ + ((cr0 + 16) * LDV_ + cd) * 4, r1_ + voff + cd);          \
        cpa_commit();                                                        \
    } while (0)

    // kick off tiles 0 and 1
    ISSUE_TILE(0, 0);
    ISSUE_TILE(1, 1);

    // ---- Q fragments directly to registers (values pre-scaled, tf32) ----
    const int r_lo = wid * 16 + g;
    const int r_hi = r_lo + 8;
    uint32_t qf[8][4];
    {
        const float* qlo = qkv + base + (size_t)(qb * QROWS + r_lo) * QKV_COLS + qoff;
        const float* qhi = qkv + base + (size_t)(qb * QROWS + r_hi) * QKV_COLS + qoff;
        #pragma unroll
        for (int ks = 0; ks < 8; ks++) {
            qf[ks][0] = __float_as_uint(qlo[8 * ks + tg]);
            qf[ks][1] = __float_as_uint(qhi[8 * ks + tg]);
            qf[ks][2] = __float_as_uint(qlo[8 * ks + tg + 4]);
            qf[ks][3] = __float_as_uint(qhi[8 * ks + tg + 4]);
        }
    }

    // P fragment-major store offsets
    const int dd0 = 2 * tg, dd1 = 2 * tg + 1;
    const int poff0 = (dd0 & 3) * 2 + (dd0 >> 2);
    const int poff1 = (dd1 & 3) * 2 + (dd1 >> 2);

    float O[8][4];
    #pragma unroll
    for (int nt = 0; nt < 8; nt++)
        #pragma unroll
        for (int i = 0; i < 4; i++) O[nt][i] = 0.f;
    float m_lo = -INFINITY, m_hi = -INFINITY, l_lo = 0.f, l_hi = 0.f;

    int ss = 0;   // stage of tile t
    for (int t = 0; t < NTILES; t++) {
        if (t == NTILES - 1) cpa_wait<0>(); else cpa_wait<1>();
        __syncthreads();

        // issue tile t+2 into the stage freed at iteration t-1
        if (t + 2 < NTILES) {
            const int ns = (ss + 2 >= 3) ? ss - 1 : ss + 2;
            ISSUE_TILE(t + 2, ns);
        }

        const float* Kst = sm + KS_OFF + ss * KS_STRIDE;
        const float* Vst = sm + VS_OFF + ss * VS_STRIDE;

        // ---- S = Q @ K^T (32 cols) ----
        float s[4][4];
        #pragma unroll
        for (int nt = 0; nt < 4; nt++)
            #pragma unroll
            for (int i = 0; i < 4; i++) s[nt][i] = 0.f;

        #pragma unroll
        for (int ks = 0; ks < 8; ks++) {
            const float* Kp = Kst + 8 * ks + tg;
            #pragma unroll
            for (int nt = 0; nt < 4; nt++) {
                const float* kr = Kp + (nt * 8 + g) * LDK_;
                uint32_t bf[2] = { __float_as_uint(kr[0]), __float_as_uint(kr[4]) };
                mma_tf32(s[nt], qf[ks], bf);
            }
        }

        // ---- online softmax (log2 domain) ----
        float rmx_lo = fmaxf(fmaxf(s[0][0], s[0][1]), fmaxf(s[1][0], s[1][1]));
        float rmx_hi = fmaxf(fmaxf(s[0][2], s[0][3]), fmaxf(s[1][2], s[1][3]));
        rmx_lo = fmaxf(rmx_lo, fmaxf(fmaxf(s[2][0], s[2][1]), fmaxf(s[3][0], s[3][1])));
        rmx_hi = fmaxf(rmx_hi, fmaxf(fmaxf(s[2][2], s[2][3]), fmaxf(s[3][2], s[3][3])));
        rmx_lo = fmaxf(rmx_lo, __shfl_xor_sync(0xffffffffu, rmx_lo, 1));
        rmx_lo = fmaxf(rmx_lo, __shfl_xor_sync(0xffffffffu, rmx_lo, 2));
        rmx_hi = fmaxf(rmx_hi, __shfl_xor_sync(0xffffffffu, rmx_hi, 1));
        rmx_hi = fmaxf(rmx_hi, __shfl_xor_sync(0xffffffffu, rmx_hi, 2));

        const float mn_lo = fmaxf(m_lo, rmx_lo);
        const float mn_hi = fmaxf(m_hi, rmx_hi);
        const float sc_lo = ex2(m_lo - mn_lo);
        const float sc_hi = ex2(m_hi - mn_hi);

        float rs_lo = 0.f, rs_hi = 0.f;
        #pragma unroll
        for (int nt = 0; nt < 4; nt++) {
            s[nt][0] = ex2(s[nt][0] - mn_lo);
            s[nt][1] = ex2(s[nt][1] - mn_lo);
            s[nt][2] = ex2(s[nt][2] - mn_hi);
            s[nt][3] = ex2(s[nt][3] - mn_hi);
            rs_lo += s[nt][0] + s[nt][1];
            rs_hi += s[nt][2] + s[nt][3];
        }
        rs_lo += __shfl_xor_sync(0xffffffffu, rs_lo, 1);
        rs_lo += __shfl_xor_sync(0xffffffffu, rs_lo, 2);
        rs_hi += __shfl_xor_sync(0xffffffffu, rs_hi, 1);
        rs_hi += __shfl_xor_sync(0xffffffffu, rs_hi, 2);

        l_lo = l_lo * sc_lo + rs_lo;   m_lo = mn_lo;
        l_hi = l_hi * sc_hi + rs_hi;   m_hi = mn_hi;

        #pragma unroll
        for (int nt = 0; nt < 8; nt++) {
            O[nt][0] *= sc_lo; O[nt][1] *= sc_lo;
            O[nt][2] *= sc_hi; O[nt][3] *= sc_hi;
        }

        // ---- store P (fragment-major, warp-private rows) ----
        #pragma unroll
        for (int nt = 0; nt < 4; nt++) {
            float* Pp = sm + PS_OFF + nt * QPL;
            Pp[r_lo * 8 + poff0] = tff(s[nt][0]);
            Pp[r_lo * 8 + poff1] = tff(s[nt][1]);
            Pp[r_hi * 8 + poff0] = tff(s[nt][2]);
            Pp[r_hi * 8 + poff1] = tff(s[nt][3]);
        }
        __syncwarp();

        // ---- O += P @ V (k = 32 rows) ----
        #pragma unroll
        for (int ks = 0; ks < 4; ks++) {
            uint32_t pa[4];
            {
                const float* Pp = sm + PS_OFF + ks * QPL;
                float2 t0 = *(const float2*)&Pp[r_lo * 8 + tg * 2];
                float2 t1 = *(const float2*)&Pp[r_hi * 8 + tg * 2];
                pa[0] = __float_as_uint(t0.x); pa[2] = __float_as_uint(t0.y);
                pa[1] = __float_as_uint(t1.x); pa[3] = __float_as_uint(t1.y);
            }
            const float* Vp  = Vst + (ks * 8 + tg) * LDV_;
            const float* Vp4 = Vp + 4 * LDV_;
            #pragma unroll
            for (int nt = 0; nt < 8; nt++) {
                uint32_t bv[2] = { __float_as_uint(Vp[nt * 8 + g]),
                                   __float_as_uint(Vp4[nt * 8 + g]) };
                mma_tf32(O[nt], pa, bv);
            }
        }

        ss = (ss + 1 >= 3) ? 0 : ss + 1;
    }
    #undef ISSUE_TILE

    // ---- finalize + write [B,N,D] ----
    const float il_lo = 1.f / l_lo;
    const float il_hi = 1.f / l_hi;
    const int n_lo = qb * QROWS + r_lo;
    const int n_hi = n_lo + 8;
    #pragma unroll
    for (int nt = 0; nt < 8; nt++) {
        const int c = h * HD_ + nt * 8 + 2 * tg;
        float2 vlo = make_float2(O[nt][0] * il_lo, O[nt][1] * il_lo);
        float2 vhi = make_float2(O[nt][2] * il_hi, O[nt][3] * il_hi);
        *(float2*)&out[((size_t)b * N_ + n_lo) * D_ + c] = vlo;
        *(float2*)&out[((size_t)b * N_ + n_hi) * D_ + c] = vhi;
    }
}

// ---------------------------------------------------------------------------
// Launch
// ---------------------------------------------------------------------------
extern "C" void kernel_launch(void* const* d_in, const int* in_sizes, int n_in,
                              void* d_out, int out_size)
{
    const float* x      = (const float*)d_in[0];
    const float* w_qkv  = (const float*)d_in[1];
    const float* w_proj = (const float*)d_in[2];
    const float* b_proj = (const float*)d_in[3];
    float* out = (float*)d_out;

    float *qkv, *att, *wqkvT, *wprojT;
    cudaGetSymbolAddress((void**)&qkv, g_qkv);
    cudaGetSymbolAddress((void**)&att, g_att);
    cudaGetSymbolAddress((void**)&wqkvT, g_wqkvT);
    cudaGetSymbolAddress((void**)&wprojT, g_wprojT);

    cudaFuncSetAttribute(attn_tc, cudaFuncAttributeMaxDynamicSharedMemorySize, AT_SMEM);
    cudaFuncSetAttribute((const void*)gemm_ff<false, true>,
                         cudaFuncAttributeMaxDynamicSharedMemorySize, FF_SMEM);
    cudaFuncSetAttribute((const void*)gemm_ff<true, false>,
                         cudaFuncAttributeMaxDynamicSharedMemorySize, FF_SMEM);

    const float QSC = 0.18033688011112042f;   // 0.125 * log2(e)

    // 0) transpose weights to K-major; pre-scale Q columns of W_qkv
    transpose_k<<<dim3(QKV_COLS / 32, D_ / 32), dim3(32, 8)>>>(
        w_qkv, wqkvT, D_, QKV_COLS, D_, QSC);
    transpose_k<<<dim3(D_ / 32, D_ / 32), dim3(32, 8)>>>(
        w_proj, wprojT, D_, D_, 0, 1.0f);

    // 1) QKV = X @ W_qkv  (outputs tf32-rounded; Q pre-scaled)
    gemm_ff<false, true><<<dim3(QKV_COLS / 128, M_ / 128), 256, FF_SMEM>>>(
        x, wqkvT, nullptr, qkv, QKV_COLS, D_);

    // 2) fused flash attention -> [B,N,D]
    attn_tc<<<dim3(N_ / QROWS, B_ * H_), 256, AT_SMEM>>>(qkv, att);

    // 3) OUT = ATT @ W_proj + b
    gemm_ff<true, false><<<dim3(D_ / 128, M_ / 128), 256, FF_SMEM>>>(
        att, wprojT, b_proj, out, D_, D_);
}

// round 10
// speedup vs baseline: 1.1631x; 1.0185x over previous
#include <cuda_runtime.h>
#include <math.h>
#include <stdint.h>

// ---------------------------------------------------------------------------
// Problem constants
// ---------------------------------------------------------------------------
#define B_   4
#define N_   2048
#define D_   768
#define H_   12
#define HD_  64
#define M_   (B_ * N_)             // 8192
#define QKV_COLS (3 * D_)          // 2304

// Scratch (alloc-free rule)
__device__ float g_qkv[(size_t)M_ * QKV_COLS];
__device__ float g_att[(size_t)M_ * D_];
__device__ float g_xr[(size_t)M_ * D_];            // tf32-rounded X
__device__ float g_wqkvT[(size_t)QKV_COLS * D_];   // [N=2304][K=768], rounded
__device__ float g_wprojT[(size_t)D_ * D_];        // [N=768][K=768], rounded

// ---------------------------------------------------------------------------
// tf32 helpers (legacy mma path — harness targets sm_100 base, no tcgen05)
// ---------------------------------------------------------------------------
__device__ __forceinline__ float tff(float x) {   // tf32 round, keep float
    float r;
    asm("{ .reg .b32 t; cvt.rna.tf32.f32 t, %1; mov.b32 %0, t; }" : "=f"(r) : "f"(x));
    return r;
}

__device__ __forceinline__ float ex2(float x) {
    float y;
    asm("ex2.approx.ftz.f32 %0, %1;" : "=f"(y) : "f"(x));
    return y;
}

__device__ __forceinline__ void mma_tf32(float* c, const uint32_t* a, const uint32_t* b) {
    asm volatile(
        "mma.sync.aligned.m16n8k8.row.col.f32.tf32.tf32.f32 "
        "{%0,%1,%2,%3}, {%4,%5,%6,%7}, {%8,%9}, {%0,%1,%2,%3};"
        : "+f"(c[0]), "+f"(c[1]), "+f"(c[2]), "+f"(c[3])
        : "r"(a[0]), "r"(a[1]), "r"(a[2]), "r"(a[3]), "r"(b[0]), "r"(b[1]));
}

__device__ __forceinline__ void cpa16(uint32_t dst, const float* src) {
    asm volatile("cp.async.ca.shared.global [%0], [%1], 16;"
                 :: "r"(dst), "l"(src) : "memory");
}
__device__ __forceinline__ void cpa_commit() {
    asm volatile("cp.async.commit_group;" ::: "memory");
}
template<int NN>
__device__ __forceinline__ void cpa_wait() {
    asm volatile("cp.async.wait_group %0;" :: "n"(NN) : "memory");
}

__device__ __forceinline__ uint32_t smem_u32(const void* p) {
    uint32_t a;
    asm("{ .reg .u64 t; cvta.to.shared.u64 t, %1; cvt.u32.u64 %0, t; }" : "=r"(a) : "l"(p));
    return a;
}

// ---------------------------------------------------------------------------
// One-pass tf32 rounding copy (X)
// ---------------------------------------------------------------------------
__global__ __launch_bounds__(256) void round_tf(
    const float* __restrict__ in, float* __restrict__ out, int n4)
{
    const int i = blockIdx.x * 256 + threadIdx.x;
    if (i < n4) {
        float4 v = ((const float4*)in)[i];
        v.x = tff(v.x); v.y = tff(v.y); v.z = tff(v.z); v.w = tff(v.w);
        ((float4*)out)[i] = v;
    }
}

// ---------------------------------------------------------------------------
// Weight transpose + tf32 round: out[N][K] = round(in[K][N] * scale_row)
// ---------------------------------------------------------------------------
__global__ __launch_bounds__(256) void transpose_k(
    const float* __restrict__ in, float* __restrict__ out, int K, int N,
    int qrows, float qscale)
{
    __shared__ float t[32][33];
    const int kb = blockIdx.y * 32, nb = blockIdx.x * 32;
    const int x = threadIdx.x, y = threadIdx.y;
    #pragma unroll
    for (int i = 0; i < 32; i += 8)
        t[y + i][x] = in[(size_t)(kb + y + i) * N + nb + x];
    __syncthreads();
    #pragma unroll
    for (int i = 0; i < 32; i += 8) {
        const int n = nb + y + i;
        const float s = (n < qrows) ? qscale : 1.0f;
        out[(size_t)n * K + kb + x] = tff(t[x][y + i] * s);
    }
}

// ---------------------------------------------------------------------------
// tf32 GEMM, fragment-major smem + 2-stage pipeline. Inputs pre-rounded ->
// zero conversions in the hot loop. Optional tf32-rounded output.
// ---------------------------------------------------------------------------
#define FF_SMEM (16512 * 4)

template<bool BIAS, bool ROUND>
__global__ __launch_bounds__(256, 2) void gemm_ff(
    const float* __restrict__ A, const float* __restrict__ WT,
    const float* __restrict__ bias, float* __restrict__ C,
    int N, int K)
{
    extern __shared__ float smf[];

    const int tid  = threadIdx.x;
    const int lane = tid & 31;
    const int wid  = tid >> 5;
    const int g    = lane >> 2;
    const int tg   = lane & 3;
    const int wm   = wid & 3;
    const int wn   = wid >> 2;
    const int row0 = blockIdx.y * 128;
    const int col0 = blockIdx.x * 128;
    const int KT   = K / 32;

    float acc[2][8][4];
    #pragma unroll
    for (int mt = 0; mt < 2; mt++)
        #pragma unroll
        for (int nt = 0; nt < 8; nt++)
            #pragma unroll
            for (int i = 0; i < 4; i++) acc[mt][nt][i] = 0.f;

    const int lrow = tid >> 3;
    const int lkq  = tid & 7;
    const int ks0  = lkq >> 1;
    const int m0   = lkq & 1;
    const int kA   = 8 * ks0 + 2 * m0;

    const float* Ap = A  + (size_t)(row0 + lrow) * K + kA;
    const float* Bp = WT + (size_t)(col0 + lrow) * K + kA;

    float2 rg[2][4][2];

    #define LOAD_TILE(t_) do {                                               \
        const size_t koff_ = (size_t)(t_) * 32;                             \
        _Pragma("unroll")                                                    \
        for (int i_ = 0; i_ < 4; i_++) {                                     \
            const float* a_ = Ap + (size_t)(i_ * 32) * K + koff_;            \
            const float* b_ = Bp + (size_t)(i_ * 32) * K + koff_;            \
            rg[0][i_][0] = *(const float2*)a_;                               \
            rg[0][i_][1] = *(const float2*)(a_ + 4);                         \
            rg[1][i_][0] = *(const float2*)b_;                               \
            rg[1][i_][1] = *(const float2*)(b_ + 4);                         \
        }                                                                    \
    } while (0)

    #define STORE_TILE(s_) do {                                              \
        float* baseA_ = smf + (s_) * 8256 + ks0 * 1032 + 4 * m0;             \
        float* baseB_ = baseA_ + 4128;                                       \
        _Pragma("unroll")                                                    \
        for (int i_ = 0; i_ < 4; i_++) {                                     \
            const int r_ = lrow + 32 * i_;                                   \
            *(float4*)(baseA_ + r_ * 8) =                                    \
                make_float4(rg[0][i_][0].x, rg[0][i_][1].x,                  \
                            rg[0][i_][0].y, rg[0][i_][1].y);                 \
            *(float4*)(baseB_ + r_ * 8) =                                    \
                make_float4(rg[1][i_][0].x, rg[1][i_][1].x,                  \
                            rg[1][i_][0].y, rg[1][i_][1].y);                 \
        }                                                                    \
    } while (0)

    LOAD_TILE(0);
    STORE_TILE(0);
    if (KT > 1) LOAD_TILE(1);
    __syncthreads();

    for (int t = 0; t < KT; t++) {
        const int s = t & 1;

        if (t + 1 < KT) {
            STORE_TILE(s ^ 1);
            if (t + 2 < KT) LOAD_TILE(t + 2);
        }

        const float2* As2 = (const float2*)(smf + s * 8256);
        const float2* Bs2 = (const float2*)(smf + s * 8256 + 4128);

        #pragma unroll
        for (int ks = 0; ks < 4; ks++) {
            const float2* Ak = As2 + ks * 516;
            const float2* Bk = Bs2 + ks * 516;
            uint32_t af[2][4];
            #pragma unroll
            for (int mt = 0; mt < 2; mt++) {
                const int r = wm * 32 + mt * 16 + g;
                float2 v1 = Ak[r * 4 + tg];
                float2 v2 = Ak[(r + 8) * 4 + tg];
                af[mt][0] = __float_as_uint(v1.x);
                af[mt][1] = __float_as_uint(v2.x);
                af[mt][2] = __float_as_uint(v1.y);
                af[mt][3] = __float_as_uint(v2.y);
            }
            #pragma unroll
            for (int nt = 0; nt < 8; nt++) {
                const int c = wn * 64 + nt * 8 + g;
                float2 w = Bk[c * 4 + tg];
                uint32_t bf[2] = { __float_as_uint(w.x), __float_as_uint(w.y) };
                mma_tf32(acc[0][nt], af[0], bf);
                mma_tf32(acc[1][nt], af[1], bf);
            }
        }
        __syncthreads();
    }

    #undef LOAD_TILE
    #undef STORE_TILE

    #pragma unroll
    for (int mt = 0; mt < 2; mt++) {
        const int r_lo = row0 + wm * 32 + mt * 16 + g;
        const int r_hi = r_lo + 8;
        #pragma unroll
        for (int nt = 0; nt < 8; nt++) {
            const int c = col0 + wn * 64 + nt * 8 + 2 * tg;
            float2 v0 = make_float2(acc[mt][nt][0], acc[mt][nt][1]);
            float2 v1 = make_float2(acc[mt][nt][2], acc[mt][nt][3]);
            if (BIAS) {
                float2 bb = *(const float2*)&bias[c];
                v0.x += bb.x; v0.y += bb.y;
                v1.x += bb.x; v1.y += bb.y;
            }
            if (ROUND) {
                v0.x = tff(v0.x); v0.y = tff(v0.y);
                v1.x = tff(v1.x); v1.y = tff(v1.y);
            }
            *(float2*)&C[(size_t)r_lo * N + c] = v0;
            *(float2*)&C[(size_t)r_hi * N + c] = v1;
        }
    }
}

// ---------------------------------------------------------------------------
// Flash attention, tf32 mma, cp.async 3-stage KV ring, Q fragments in regs.
// Inputs in g_qkv are already tf32-rounded; Q part pre-scaled by 0.125*log2e.
// P fed to mma as raw fp32 (hardware truncation to tf32; P in (0,1]).
// Output rounded (feeds proj GEMM raw).
// ---------------------------------------------------------------------------
#define QPL   1032
#define PS_OFF 0
#define KS_OFF 4128
#define KS_STRIDE 2176
#define VS_OFF 10656
#define VS_STRIDE 2304
#define LDK_  68
#define LDV_  72
#define QROWS 128
#define NTILES (N_ / 32)
#define AT_SMEM ((VS_OFF + 3 * VS_STRIDE) * 4)   // 70272 B

__global__ __launch_bounds__(256, 2) void attn_tc(
    const float* __restrict__ qkv, float* __restrict__ out)
{
    extern __shared__ float sm[];
    const uint32_t sb4 = smem_u32(sm);

    const int tid  = threadIdx.x;
    const int lane = tid & 31;
    const int wid  = tid >> 5;
    const int g    = lane >> 2;
    const int tg   = lane & 3;
    const int qb   = blockIdx.x;            // 0..15
    const int bh   = blockIdx.y;            // 0..47
    const int b    = bh / H_;
    const int h    = bh % H_;

    const size_t base = (size_t)b * N_ * QKV_COLS;
    const int qoff = h * HD_;
    const int koff = D_ + h * HD_;
    const int voff = 2 * D_ + h * HD_;

    // cp.async loader mapping: rows cr0, cr0+16; 16B chunk at col cd
    const int cr0 = tid >> 4;                // 0..15
    const int cd  = (tid & 15) * 4;          // 0..60

    // running tile pointer (strength-reduced)
    const float* tp = qkv + base + (size_t)cr0 * QKV_COLS;
    const size_t TILE_STEP = (size_t)32 * QKV_COLS;

    #define ISSUE_TILE(ptr_, ss_) do {                                       \
        const float* r1_ = (ptr_) + (size_t)16 * QKV_COLS;                   \
        const uint32_t kd_ = sb4 + (KS_OFF + (ss_) * KS_STRIDE) * 4;         \
        const uint32_t vd_ = sb4 + (VS_OFF + (ss_) * VS_STRIDE) * 4;         \
        cpa16(kd_ + (cr0 * LDK_ + cd) * 4,        (ptr_) + koff + cd);       \
        cpa16(kd_ + ((cr0 + 16) * LDK_ + cd) * 4, r1_ + koff + cd);          \
        cpa16(vd_ + (cr0 * LDV_ + cd) * 4,        (ptr_) + voff + cd);       \
        cpa16(vd_ + ((cr0 + 16) * LDV_ + cd) * 4, r1_ + voff + cd);          \
        cpa_commit();                                                        \
    } while (0)

    // kick off tiles 0 and 1
    ISSUE_TILE(tp, 0);
    ISSUE_TILE(tp + TILE_STEP, 1);
    const float* tp2 = tp + 2 * TILE_STEP;   // pointer for tile t+2

    // ---- Q fragments directly to registers (values pre-scaled, tf32) ----
    const int r_lo = wid * 16 + g;
    const int r_hi = r_lo + 8;
    uint32_t qf[8][4];
    {
        const float* qlo = qkv + base + (size_t)(qb * QROWS + r_lo) * QKV_COLS + qoff;
        const float* qhi = qkv + base + (size_t)(qb * QROWS + r_hi) * QKV_COLS + qoff;
        #pragma unroll
        for (int ks = 0; ks < 8; ks++) {
            qf[ks][0] = __float_as_uint(qlo[8 * ks + tg]);
            qf[ks][1] = __float_as_uint(qhi[8 * ks + tg]);
            qf[ks][2] = __float_as_uint(qlo[8 * ks + tg + 4]);
            qf[ks][3] = __float_as_uint(qhi[8 * ks + tg + 4]);
        }
    }

    // P fragment-major store offsets
    const int dd0 = 2 * tg, dd1 = 2 * tg + 1;
    const int poff0 = (dd0 & 3) * 2 + (dd0 >> 2);
    const int poff1 = (dd1 & 3) * 2 + (dd1 >> 2);

    float O[8][4];
    #pragma unroll
    for (int nt = 0; nt < 8; nt++)
        #pragma unroll
        for (int i = 0; i < 4; i++) O[nt][i] = 0.f;
    float m_lo = -INFINITY, m_hi = -INFINITY, l_lo = 0.f, l_hi = 0.f;

    int ss = 0;   // stage of tile t
    for (int t = 0; t < NTILES; t++) {
        if (t == NTILES - 1) cpa_wait<0>(); else cpa_wait<1>();
        __syncthreads();

        // issue tile t+2 into the stage freed at iteration t-1
        if (t + 2 < NTILES) {
            const int ns = (ss + 2 >= 3) ? ss - 1 : ss + 2;
            ISSUE_TILE(tp2, ns);
            tp2 += TILE_STEP;
        }

        const float* Kst = sm + KS_OFF + ss * KS_STRIDE;
        const float* Vst = sm + VS_OFF + ss * VS_STRIDE;

        // ---- S = Q @ K^T (32 cols) ----
        float s[4][4];
        #pragma unroll
        for (int nt = 0; nt < 4; nt++)
            #pragma unroll
            for (int i = 0; i < 4; i++) s[nt][i] = 0.f;

        #pragma unroll
        for (int ks = 0; ks < 8; ks++) {
            const float* Kp = Kst + 8 * ks + tg;
            #pragma unroll
            for (int nt = 0; nt < 4; nt++) {
                const float* kr = Kp + (nt * 8 + g) * LDK_;
                uint32_t bf[2] = { __float_as_uint(kr[0]), __float_as_uint(kr[4]) };
                mma_tf32(s[nt], qf[ks], bf);
            }
        }

        // ---- online softmax (log2 domain) ----
        float rmx_lo = fmaxf(fmaxf(s[0][0], s[0][1]), fmaxf(s[1][0], s[1][1]));
        float rmx_hi = fmaxf(fmaxf(s[0][2], s[0][3]), fmaxf(s[1][2], s[1][3]));
        rmx_lo = fmaxf(rmx_lo, fmaxf(fmaxf(s[2][0], s[2][1]), fmaxf(s[3][0], s[3][1])));
        rmx_hi = fmaxf(rmx_hi, fmaxf(fmaxf(s[2][2], s[2][3]), fmaxf(s[3][2], s[3][3])));
        rmx_lo = fmaxf(rmx_lo, __shfl_xor_sync(0xffffffffu, rmx_lo, 1));
        rmx_lo = fmaxf(rmx_lo, __shfl_xor_sync(0xffffffffu, rmx_lo, 2));
        rmx_hi = fmaxf(rmx_hi, __shfl_xor_sync(0xffffffffu, rmx_hi, 1));
        rmx_hi = fmaxf(rmx_hi, __shfl_xor_sync(0xffffffffu, rmx_hi, 2));

        const float mn_lo = fmaxf(m_lo, rmx_lo);
        const float mn_hi = fmaxf(m_hi, rmx_hi);
        const float sc_lo = ex2(m_lo - mn_lo);
        const float sc_hi = ex2(m_hi - mn_hi);

        float rs_lo = 0.f, rs_hi = 0.f;
        #pragma unroll
        for (int nt = 0; nt < 4; nt++) {
            s[nt][0] = ex2(s[nt][0] - mn_lo);
            s[nt][1] = ex2(s[nt][1] - mn_lo);
            s[nt][2] = ex2(s[nt][2] - mn_hi);
            s[nt][3] = ex2(s[nt][3] - mn_hi);
            rs_lo += s[nt][0] + s[nt][1];
            rs_hi += s[nt][2] + s[nt][3];
        }
        rs_lo += __shfl_xor_sync(0xffffffffu, rs_lo, 1);
        rs_lo += __shfl_xor_sync(0xffffffffu, rs_lo, 2);
        rs_hi += __shfl_xor_sync(0xffffffffu, rs_hi, 1);
        rs_hi += __shfl_xor_sync(0xffffffffu, rs_hi, 2);

        l_lo = l_lo * sc_lo + rs_lo;   m_lo = mn_lo;
        l_hi = l_hi * sc_hi + rs_hi;   m_hi = mn_hi;

        #pragma unroll
        for (int nt = 0; nt < 8; nt++) {
            O[nt][0] *= sc_lo; O[nt][1] *= sc_lo;
            O[nt][2] *= sc_hi; O[nt][3] *= sc_hi;
        }

        // ---- store P raw (mma truncates to tf32; P in (0,1]) ----
        #pragma unroll
        for (int nt = 0; nt < 4; nt++) {
            float* Pp = sm + PS_OFF + nt * QPL;
            Pp[r_lo * 8 + poff0] = s[nt][0];
            Pp[r_lo * 8 + poff1] = s[nt][1];
            Pp[r_hi * 8 + poff0] = s[nt][2];
            Pp[r_hi * 8 + poff1] = s[nt][3];
        }
        __syncwarp();

        // ---- O += P @ V (k = 32 rows) ----
        #pragma unroll
        for (int ks = 0; ks < 4; ks++) {
            uint32_t pa[4];
            {
                const float* Pp = sm + PS_OFF + ks * QPL;
                float2 t0 = *(const float2*)&Pp[r_lo * 8 + tg * 2];
                float2 t1 = *(const float2*)&Pp[r_hi * 8 + tg * 2];
                pa[0] = __float_as_uint(t0.x); pa[2] = __float_as_uint(t0.y);
                pa[1] = __float_as_uint(t1.x); pa[3] = __float_as_uint(t1.y);
            }
            const float* Vp  = Vst + (ks * 8 + tg) * LDV_;
            const float* Vp4 = Vp + 4 * LDV_;
            #pragma unroll
            for (int nt = 0; nt < 8; nt++) {
                uint32_t bv[2] = { __float_as_uint(Vp[nt * 8 + g]),
                                   __float_as_uint(Vp4[nt * 8 + g]) };
                mma_tf32(O[nt], pa, bv);
            }
        }

        ss = (ss + 1 >= 3) ? 0 : ss + 1;
    }
    #undef ISSUE_TILE

    // ---- finalize + write [B,N,D], tf32-rounded for the proj GEMM ----
    const float il_lo = 1.f / l_lo;
    const float il_hi = 1.f / l_hi;
    const int n_lo = qb * QROWS + r_lo;
    const int n_hi = n_lo + 8;
    #pragma unroll
    for (int nt = 0; nt < 8; nt++) {
        const int c = h * HD_ + nt * 8 + 2 * tg;
        float2 vlo = make_float2(tff(O[nt][0] * il_lo), tff(O[nt][1] * il_lo));
        float2 vhi = make_float2(tff(O[nt][2] * il_hi), tff(O[nt][3] * il_hi));
        *(float2*)&out[((size_t)b * N_ + n_lo) * D_ + c] = vlo;
        *(float2*)&out[((size_t)b * N_ + n_hi) * D_ + c] = vhi;
    }
}

// ---------------------------------------------------------------------------
// Launch
// ---------------------------------------------------------------------------
extern "C" void kernel_launch(void* const* d_in, const int* in_sizes, int n_in,
                              void* d_out, int out_size)
{
    const float* x      = (const float*)d_in[0];
    const float* w_qkv  = (const float*)d_in[1];
    const float* w_proj = (const float*)d_in[2];
    const float* b_proj = (const float*)d_in[3];
    float* out = (float*)d_out;

    float *qkv, *att, *xr, *wqkvT, *wprojT;
    cudaGetSymbolAddress((void**)&qkv, g_qkv);
    cudaGetSymbolAddress((void**)&att, g_att);
    cudaGetSymbolAddress((void**)&xr, g_xr);
    cudaGetSymbolAddress((void**)&wqkvT, g_wqkvT);
    cudaGetSymbolAddress((void**)&wprojT, g_wprojT);

    cudaFuncSetAttribute(attn_tc, cudaFuncAttributeMaxDynamicSharedMemorySize, AT_SMEM);
    cudaFuncSetAttribute((const void*)gemm_ff<false, true>,
                         cudaFuncAttributeMaxDynamicSharedMemorySize, FF_SMEM);
    cudaFuncSetAttribute((const void*)gemm_ff<true, false>,
                         cudaFuncAttributeMaxDynamicSharedMemorySize, FF_SMEM);

    const float QSC = 0.18033688011112042f;   // 0.125 * log2(e)

    // 0) pre-round X; transpose+round weights (Q columns pre-scaled)
    round_tf<<<(M_ * D_ / 4 + 255) / 256, 256>>>(x, xr, M_ * D_ / 4);
    transpose_k<<<dim3(QKV_COLS / 32, D_ / 32), dim3(32, 8)>>>(
        w_qkv, wqkvT, D_, QKV_COLS, D_, QSC);
    transpose_k<<<dim3(D_ / 32, D_ / 32), dim3(32, 8)>>>(
        w_proj, wprojT, D_, D_, 0, 1.0f);

    // 1) QKV = Xr @ W_qkv  (outputs tf32-rounded; Q pre-scaled)
    gemm_ff<false, true><<<dim3(QKV_COLS / 128, M_ / 128), 256, FF_SMEM>>>(
        xr, wqkvT, nullptr, qkv, QKV_COLS, D_);

    // 2) fused flash attention -> [B,N,D] (rounded)
    attn_tc<<<dim3(N_ / QROWS, B_ * H_), 256, AT_SMEM>>>(qkv, att);

    // 3) OUT = ATT @ W_proj + b  (final output, not rounded)
    gemm_ff<true, false><<<dim3(D_ / 128, M_ / 128), 256, FF_SMEM>>>(
        att, wprojT, b_proj, out, D_, D_);
}

// round 11
// speedup vs baseline: 1.1759x; 1.0110x over previous
#include <cuda_runtime.h>
#include <math.h>
#include <stdint.h>

// ---------------------------------------------------------------------------
// Problem constants
// ---------------------------------------------------------------------------
#define B_   4
#define N_   2048
#define D_   768
#define H_   12
#define HD_  64
#define M_   (B_ * N_)             // 8192
#define QKV_COLS (3 * D_)          // 2304

// Scratch (alloc-free rule)
__device__ float g_qkv[(size_t)M_ * QKV_COLS];     // perm8 layout on d
__device__ float g_att[(size_t)M_ * D_];           // perm8 layout on d
__device__ float g_xr[(size_t)M_ * D_];            // tf32-rounded X, perm8 on k
__device__ float g_wqkvT[(size_t)QKV_COLS * D_];   // [N][K], perm8 on k
__device__ float g_wprojT[(size_t)D_ * D_];        // [N][K], perm8 on k

// perm within each 8-group: d -> (d&3)*2 + ((d>>2)&1)
// group words ordered [x0,x4,x1,x5,x2,x6,x3,x7] so pair (k,k+4) is adjacent.

// ---------------------------------------------------------------------------
// tf32 helpers (legacy mma path — harness targets sm_100 base, no tcgen05)
// ---------------------------------------------------------------------------
__device__ __forceinline__ float tff(float x) {
    float r;
    asm("{ .reg .b32 t; cvt.rna.tf32.f32 t, %1; mov.b32 %0, t; }" : "=f"(r) : "f"(x));
    return r;
}

__device__ __forceinline__ float ex2(float x) {
    float y;
    asm("ex2.approx.ftz.f32 %0, %1;" : "=f"(y) : "f"(x));
    return y;
}

__device__ __forceinline__ void mma_tf32(float* c, const uint32_t* a, const uint32_t* b) {
    asm volatile(
        "mma.sync.aligned.m16n8k8.row.col.f32.tf32.tf32.f32 "
        "{%0,%1,%2,%3}, {%4,%5,%6,%7}, {%8,%9}, {%0,%1,%2,%3};"
        : "+f"(c[0]), "+f"(c[1]), "+f"(c[2]), "+f"(c[3])
        : "r"(a[0]), "r"(a[1]), "r"(a[2]), "r"(a[3]), "r"(b[0]), "r"(b[1]));
}

__device__ __forceinline__ void cpa16(uint32_t dst, const float* src) {
    asm volatile("cp.async.ca.shared.global [%0], [%1], 16;"
                 :: "r"(dst), "l"(src) : "memory");
}
__device__ __forceinline__ void cpa_commit() {
    asm volatile("cp.async.commit_group;" ::: "memory");
}
template<int NN>
__device__ __forceinline__ void cpa_wait() {
    asm volatile("cp.async.wait_group %0;" :: "n"(NN) : "memory");
}

__device__ __forceinline__ uint32_t smem_u32(const void* p) {
    uint32_t a;
    asm("{ .reg .u64 t; cvta.to.shared.u64 t, %1; cvt.u32.u64 %0, t; }" : "=r"(a) : "l"(p));
    return a;
}

// ---------------------------------------------------------------------------
// tf32 round + perm8 interleave (X): 8 floats per thread
// ---------------------------------------------------------------------------
__global__ __launch_bounds__(256) void round_perm(
    const float* __restrict__ in, float* __restrict__ out, int n8)
{
    const int i = blockIdx.x * 256 + threadIdx.x;
    if (i < n8) {
        float4 a = ((const float4*)in)[2 * i];
        float4 b = ((const float4*)in)[2 * i + 1];
        float4 o0 = make_float4(tff(a.x), tff(b.x), tff(a.y), tff(b.y));
        float4 o1 = make_float4(tff(a.z), tff(b.z), tff(a.w), tff(b.w));
        ((float4*)out)[2 * i]     = o0;
        ((float4*)out)[2 * i + 1] = o1;
    }
}

// ---------------------------------------------------------------------------
// Weight transpose + round + perm8 on k: out[N][Kperm] = round(in[K][N]*s)
// ---------------------------------------------------------------------------
__global__ __launch_bounds__(256) void transpose_k(
    const float* __restrict__ in, float* __restrict__ out, int K, int N,
    int qrows, float qscale)
{
    __shared__ float t[32][33];
    const int kb = blockIdx.y * 32, nb = blockIdx.x * 32;
    const int x = threadIdx.x, y = threadIdx.y;
    #pragma unroll
    for (int i = 0; i < 32; i += 8)
        t[y + i][x] = in[(size_t)(kb + y + i) * N + nb + x];
    __syncthreads();
    const int k  = kb + x;
    const int kp = (k & ~7) | (((k & 3) << 1) | ((k >> 2) & 1));
    #pragma unroll
    for (int i = 0; i < 32; i += 8) {
        const int n = nb + y + i;
        const float s = (n < qrows) ? qscale : 1.0f;
        out[(size_t)n * K + kp] = tff(t[x][y + i] * s);
    }
}

// ---------------------------------------------------------------------------
// tf32 GEMM on perm8 inputs: fragment-major smem, LDG.128 loads, direct STS.
// PERMOUT: write output with perm8 on columns (for downstream consumers).
// ---------------------------------------------------------------------------
#define FF_SMEM (16512 * 4)

template<bool BIAS, bool ROUND, bool PERMOUT>
__global__ __launch_bounds__(256, 2) void gemm_ff(
    const float* __restrict__ A, const float* __restrict__ WT,
    const float* __restrict__ bias, float* __restrict__ C,
    int N, int K)
{
    extern __shared__ float smf[];

    const int tid  = threadIdx.x;
    const int lane = tid & 31;
    const int wid  = tid >> 5;
    const int g    = lane >> 2;
    const int tg   = lane & 3;
    const int wm   = wid & 3;
    const int wn   = wid >> 2;
    const int row0 = blockIdx.y * 128;
    const int col0 = blockIdx.x * 128;
    const int KT   = K / 32;

    float acc[2][8][4];
    #pragma unroll
    for (int mt = 0; mt < 2; mt++)
        #pragma unroll
        for (int nt = 0; nt < 8; nt++)
            #pragma unroll
            for (int i = 0; i < 4; i++) acc[mt][nt][i] = 0.f;

    const int lrow = tid >> 3;
    const int lkq  = tid & 7;
    const int ks0  = lkq >> 1;
    const int m0   = lkq & 1;
    const int kA   = 8 * ks0 + 4 * m0;   // perm-space float4 offset

    const float* Ap = A  + (size_t)(row0 + lrow) * K + kA;
    const float* Bp = WT + (size_t)(col0 + lrow) * K + kA;

    float4 rs[2][4];

    #define LOAD_TILE(t_) do {                                               \
        const size_t koff_ = (size_t)(t_) * 32;                             \
        _Pragma("unroll")                                                    \
        for (int i_ = 0; i_ < 4; i_++) {                                     \
            rs[0][i_] = *(const float4*)(Ap + (size_t)(i_ * 32) * K + koff_);\
            rs[1][i_] = *(const float4*)(Bp + (size_t)(i_ * 32) * K + koff_);\
        }                                                                    \
    } while (0)

    #define STORE_TILE(s_) do {                                              \
        float* baseA_ = smf + (s_) * 8256 + ks0 * 1032 + 4 * m0;             \
        float* baseB_ = baseA_ + 4128;                                       \
        _Pragma("unroll")                                                    \
        for (int i_ = 0; i_ < 4; i_++) {                                     \
            const int r_ = lrow + 32 * i_;                                   \
            *(float4*)(baseA_ + r_ * 8) = rs[0][i_];                         \
            *(float4*)(baseB_ + r_ * 8) = rs[1][i_];                         \
        }                                                                    \
    } while (0)

    LOAD_TILE(0);
    STORE_TILE(0);
    if (KT > 1) LOAD_TILE(1);
    __syncthreads();

    for (int t = 0; t < KT; t++) {
        const int s = t & 1;

        if (t + 1 < KT) {
            STORE_TILE(s ^ 1);
            if (t + 2 < KT) LOAD_TILE(t + 2);
        }

        const float2* As2 = (const float2*)(smf + s * 8256);
        const float2* Bs2 = (const float2*)(smf + s * 8256 + 4128);

        #pragma unroll
        for (int ks = 0; ks < 4; ks++) {
            const float2* Ak = As2 + ks * 516;
            const float2* Bk = Bs2 + ks * 516;
            uint32_t af[2][4];
            #pragma unroll
            for (int mt = 0; mt < 2; mt++) {
                const int r = wm * 32 + mt * 16 + g;
                float2 v1 = Ak[r * 4 + tg];
                float2 v2 = Ak[(r + 8) * 4 + tg];
                af[mt][0] = __float_as_uint(v1.x);
                af[mt][1] = __float_as_uint(v2.x);
                af[mt][2] = __float_as_uint(v1.y);
                af[mt][3] = __float_as_uint(v2.y);
            }
            #pragma unroll
            for (int nt = 0; nt < 8; nt++) {
                const int c = wn * 64 + nt * 8 + g;
                float2 w = Bk[c * 4 + tg];
                uint32_t bf[2] = { __float_as_uint(w.x), __float_as_uint(w.y) };
                mma_tf32(acc[0][nt], af[0], bf);
                mma_tf32(acc[1][nt], af[1], bf);
            }
        }
        __syncthreads();
    }

    #undef LOAD_TILE
    #undef STORE_TILE

    // perm positions for output pair (2tg, 2tg+1) within its 8-group
    const int dl = 2 * tg;
    const int p0 = ((dl & 3) << 1) + (dl >> 2);
    const int p1 = (((dl + 1) & 3) << 1) + ((dl + 1) >> 2);

    #pragma unroll
    for (int mt = 0; mt < 2; mt++) {
        const int r_lo = row0 + wm * 32 + mt * 16 + g;
        const int r_hi = r_lo + 8;
        #pragma unroll
        for (int nt = 0; nt < 8; nt++) {
            const int c = col0 + wn * 64 + nt * 8 + 2 * tg;
            float2 v0 = make_float2(acc[mt][nt][0], acc[mt][nt][1]);
            float2 v1 = make_float2(acc[mt][nt][2], acc[mt][nt][3]);
            if (BIAS) {
                float2 bb = *(const float2*)&bias[c];
                v0.x += bb.x; v0.y += bb.y;
                v1.x += bb.x; v1.y += bb.y;
            }
            if (ROUND) {
                v0.x = tff(v0.x); v0.y = tff(v0.y);
                v1.x = tff(v1.x); v1.y = tff(v1.y);
            }
            if (PERMOUT) {
                const int cg = c & ~7;
                C[(size_t)r_lo * N + cg + p0] = v0.x;
                C[(size_t)r_lo * N + cg + p1] = v0.y;
                C[(size_t)r_hi * N + cg + p0] = v1.x;
                C[(size_t)r_hi * N + cg + p1] = v1.y;
            } else {
                *(float2*)&C[(size_t)r_lo * N + c] = v0;
                *(float2*)&C[(size_t)r_hi * N + c] = v1;
            }
        }
    }
}

// ---------------------------------------------------------------------------
// Flash attention, tf32 mma, cp.async 3-stage KV ring, perm8 inputs.
// K fragment loads = LDS.64 (perm layout); Q = LDG.64 pairs; V scalar with
// perm'd index. Output written perm8 (feeds proj GEMM).
// ---------------------------------------------------------------------------
#define QPL   1032
#define PS_OFF 0
#define KS_OFF 4128
#define KS_STRIDE 2304
#define VS_OFF 11040
#define VS_STRIDE 2304
#define LDK_  72
#define LDV_  72
#define QROWS 128
#define NTILES (N_ / 32)
#define AT_SMEM ((VS_OFF + 3 * VS_STRIDE) * 4)   // 71808 B

__global__ __launch_bounds__(256, 2) void attn_tc(
    const float* __restrict__ qkv, float* __restrict__ out)
{
    extern __shared__ float sm[];
    const uint32_t sb4 = smem_u32(sm);

    const int tid  = threadIdx.x;
    const int lane = tid & 31;
    const int wid  = tid >> 5;
    const int g    = lane >> 2;
    const int tg   = lane & 3;
    const int qb   = blockIdx.x;            // 0..15
    const int bh   = blockIdx.y;            // 0..47
    const int b    = bh / H_;
    const int h    = bh % H_;

    const size_t base = (size_t)b * N_ * QKV_COLS;
    const int qoff = h * HD_;
    const int koff = D_ + h * HD_;
    const int voff = 2 * D_ + h * HD_;

    // cp.async loader mapping
    const int cr0 = tid >> 4;                // 0..15
    const int cd  = (tid & 15) * 4;          // 0..60

    const float* tp = qkv + base + (size_t)cr0 * QKV_COLS;
    const size_t TILE_STEP = (size_t)32 * QKV_COLS;

    #define ISSUE_TILE(ptr_, ss_) do {                                       \
        const float* r1_ = (ptr_) + (size_t)16 * QKV_COLS;                   \
        const uint32_t kd_ = sb4 + (KS_OFF + (ss_) * KS_STRIDE) * 4;         \
        const uint32_t vd_ = sb4 + (VS_OFF + (ss_) * VS_STRIDE) * 4;         \
        cpa16(kd_ + (cr0 * LDK_ + cd) * 4,        (ptr_) + koff + cd);       \
        cpa16(kd_ + ((cr0 + 16) * LDK_ + cd) * 4, r1_ + koff + cd);          \
        cpa16(vd_ + (cr0 * LDV_ + cd) * 4,        (ptr_) + voff + cd);       \
        cpa16(vd_ + ((cr0 + 16) * LDV_ + cd) * 4, r1_ + voff + cd);          \
        cpa_commit();                                                        \
    } while (0)

    ISSUE_TILE(tp, 0);
    ISSUE_TILE(tp + TILE_STEP, 1);
    const float* tp2 = tp + 2 * TILE_STEP;

    // ---- Q fragments to registers (perm layout: pair adjacent) ----
    const int r_lo = wid * 16 + g;
    const int r_hi = r_lo + 8;
    uint32_t qf[8][4];
    {
        const float* qlo = qkv + base + (size_t)(qb * QROWS + r_lo) * QKV_COLS + qoff;
        const float* qhi = qkv + base + (size_t)(qb * QROWS + r_hi) * QKV_COLS + qoff;
        #pragma unroll
        for (int ks = 0; ks < 8; ks++) {
            float2 q0 = *(const float2*)&qlo[8 * ks + 2 * tg];
            float2 q1 = *(const float2*)&qhi[8 * ks + 2 * tg];
            qf[ks][0] = __float_as_uint(q0.x);
            qf[ks][2] = __float_as_uint(q0.y);
            qf[ks][1] = __float_as_uint(q1.x);
            qf[ks][3] = __float_as_uint(q1.y);
        }
    }

    // P fragment-major store offsets
    const int dd0 = 2 * tg, dd1 = 2 * tg + 1;
    const int poff0 = (dd0 & 3) * 2 + (dd0 >> 2);
    const int poff1 = (dd1 & 3) * 2 + (dd1 >> 2);
    // V perm'd row index for PV B-fragment
    const int pg = ((g & 3) << 1) | (g >> 2);

    float O[8][4];
    #pragma unroll
    for (int nt = 0; nt < 8; nt++)
        #pragma unroll
        for (int i = 0; i < 4; i++) O[nt][i] = 0.f;
    float m_lo = -INFINITY, m_hi = -INFINITY, l_lo = 0.f, l_hi = 0.f;

    int ss = 0;
    for (int t = 0; t < NTILES; t++) {
        if (t == NTILES - 1) cpa_wait<0>(); else cpa_wait<1>();
        __syncthreads();

        if (t + 2 < NTILES) {
            const int ns = (ss + 2 >= 3) ? ss - 1 : ss + 2;
            ISSUE_TILE(tp2, ns);
            tp2 += TILE_STEP;
        }

        const float* Kst = sm + KS_OFF + ss * KS_STRIDE;
        const float* Vst = sm + VS_OFF + ss * VS_STRIDE;

        // ---- S = Q @ K^T (32 cols); K fragments are LDS.64 ----
        float s[4][4];
        #pragma unroll
        for (int nt = 0; nt < 4; nt++)
            #pragma unroll
            for (int i = 0; i < 4; i++) s[nt][i] = 0.f;

        #pragma unroll
        for (int ks = 0; ks < 8; ks++) {
            const float* Kp = Kst + 8 * ks + 2 * tg;
            #pragma unroll
            for (int nt = 0; nt < 4; nt++) {
                float2 kf = *(const float2*)&Kp[(nt * 8 + g) * LDK_];
                uint32_t bf[2] = { __float_as_uint(kf.x), __float_as_uint(kf.y) };
                mma_tf32(s[nt], qf[ks], bf);
            }
        }

        // ---- online softmax (log2 domain) ----
        float rmx_lo = fmaxf(fmaxf(s[0][0], s[0][1]), fmaxf(s[1][0], s[1][1]));
        float rmx_hi = fmaxf(fmaxf(s[0][2], s[0][3]), fmaxf(s[1][2], s[1][3]));
        rmx_lo = fmaxf(rmx_lo, fmaxf(fmaxf(s[2][0], s[2][1]), fmaxf(s[3][0], s[3][1])));
        rmx_hi = fmaxf(rmx_hi, fmaxf(fmaxf(s[2][2], s[2][3]), fmaxf(s[3][2], s[3][3])));
        rmx_lo = fmaxf(rmx_lo, __shfl_xor_sync(0xffffffffu, rmx_lo, 1));
        rmx_lo = fmaxf(rmx_lo, __shfl_xor_sync(0xffffffffu, rmx_lo, 2));
        rmx_hi = fmaxf(rmx_hi, __shfl_xor_sync(0xffffffffu, rmx_hi, 1));
        rmx_hi = fmaxf(rmx_hi, __shfl_xor_sync(0xffffffffu, rmx_hi, 2));

        const float mn_lo = fmaxf(m_lo, rmx_lo);
        const float mn_hi = fmaxf(m_hi, rmx_hi);
        const float sc_lo = ex2(m_lo - mn_lo);
        const float sc_hi = ex2(m_hi - mn_hi);

        float rs_lo = 0.f, rs_hi = 0.f;
        #pragma unroll
        for (int nt = 0; nt < 4; nt++) {
            s[nt][0] = ex2(s[nt][0] - mn_lo);
            s[nt][1] = ex2(s[nt][1] - mn_lo);
            s[nt][2] = ex2(s[nt][2] - mn_hi);
            s[nt][3] = ex2(s[nt][3] - mn_hi);
            rs_lo += s[nt][0] + s[nt][1];
            rs_hi += s[nt][2] + s[nt][3];
        }
        rs_lo += __shfl_xor_sync(0xffffffffu, rs_lo, 1);
        rs_lo += __shfl_xor_sync(0xffffffffu, rs_lo, 2);
        rs_hi += __shfl_xor_sync(0xffffffffu, rs_hi, 1);
        rs_hi += __shfl_xor_sync(0xffffffffu, rs_hi, 2);

        l_lo = l_lo * sc_lo + rs_lo;   m_lo = mn_lo;
        l_hi = l_hi * sc_hi + rs_hi;   m_hi = mn_hi;

        #pragma unroll
        for (int nt = 0; nt < 8; nt++) {
            O[nt][0] *= sc_lo; O[nt][1] *= sc_lo;
            O[nt][2] *= sc_hi; O[nt][3] *= sc_hi;
        }

        // ---- store P raw (fragment-major, warp-private rows) ----
        #pragma unroll
        for (int nt = 0; nt < 4; nt++) {
            float* Pp = sm + PS_OFF + nt * QPL;
            Pp[r_lo * 8 + poff0] = s[nt][0];
            Pp[r_lo * 8 + poff1] = s[nt][1];
            Pp[r_hi * 8 + poff0] = s[nt][2];
            Pp[r_hi * 8 + poff1] = s[nt][3];
        }
        __syncwarp();

        // ---- O += P @ V (k = 32 rows); V read with perm'd d index ----
        #pragma unroll
        for (int ks = 0; ks < 4; ks++) {
            uint32_t pa[4];
            {
                const float* Pp = sm + PS_OFF + ks * QPL;
                float2 t0 = *(const float2*)&Pp[r_lo * 8 + tg * 2];
                float2 t1 = *(const float2*)&Pp[r_hi * 8 + tg * 2];
                pa[0] = __float_as_uint(t0.x); pa[2] = __float_as_uint(t0.y);
                pa[1] = __float_as_uint(t1.x); pa[3] = __float_as_uint(t1.y);
            }
            const float* Vp  = Vst + (ks * 8 + tg) * LDV_;
            const float* Vp4 = Vp + 4 * LDV_;
            #pragma unroll
            for (int nt = 0; nt < 8; nt++) {
                uint32_t bv[2] = { __float_as_uint(Vp[nt * 8 + pg]),
                                   __float_as_uint(Vp4[nt * 8 + pg]) };
                mma_tf32(O[nt], pa, bv);
            }
        }

        ss = (ss + 1 >= 3) ? 0 : ss + 1;
    }
    #undef ISSUE_TILE

    // ---- finalize + write [B,N,D] perm8'd + tf32-rounded (for proj) ----
    const float il_lo = 1.f / l_lo;
    const float il_hi = 1.f / l_hi;
    const int n_lo = qb * QROWS + r_lo;
    const int n_hi = n_lo + 8;
    #pragma unroll
    for (int nt = 0; nt < 8; nt++) {
        const int cg = h * HD_ + nt * 8;
        float* olo = &out[((size_t)b * N_ + n_lo) * D_ + cg];
        float* ohi = &out[((size_t)b * N_ + n_hi) * D_ + cg];
        olo[poff0] = tff(O[nt][0] * il_lo);
        olo[poff1] = tff(O[nt][1] * il_lo);
        ohi[poff0] = tff(O[nt][2] * il_hi);
        ohi[poff1] = tff(O[nt][3] * il_hi);
    }
}

// ---------------------------------------------------------------------------
// Launch
// ---------------------------------------------------------------------------
extern "C" void kernel_launch(void* const* d_in, const int* in_sizes, int n_in,
                              void* d_out, int out_size)
{
    const float* x      = (const float*)d_in[0];
    const float* w_qkv  = (const float*)d_in[1];
    const float* w_proj = (const float*)d_in[2];
    const float* b_proj = (const float*)d_in[3];
    float* out = (float*)d_out;

    float *qkv, *att, *xr, *wqkvT, *wprojT;
    cudaGetSymbolAddress((void**)&qkv, g_qkv);
    cudaGetSymbolAddress((void**)&att, g_att);
    cudaGetSymbolAddress((void**)&xr, g_xr);
    cudaGetSymbolAddress((void**)&wqkvT, g_wqkvT);
    cudaGetSymbolAddress((void**)&wprojT, g_wprojT);

    cudaFuncSetAttribute(attn_tc, cudaFuncAttributeMaxDynamicSharedMemorySize, AT_SMEM);
    cudaFuncSetAttribute((const void*)gemm_ff<false, true, true>,
                         cudaFuncAttributeMaxDynamicSharedMemorySize, FF_SMEM);
    cudaFuncSetAttribute((const void*)gemm_ff<true, false, false>,
                         cudaFuncAttributeMaxDynamicSharedMemorySize, FF_SMEM);

    const float QSC = 0.18033688011112042f;   // 0.125 * log2(e)

    // 0) pre-round+perm X; transpose+round+perm weights (Q cols pre-scaled)
    round_perm<<<(M_ * D_ / 8 + 255) / 256, 256>>>(x, xr, M_ * D_ / 8);
    transpose_k<<<dim3(QKV_COLS / 32, D_ / 32), dim3(32, 8)>>>(
        w_qkv, wqkvT, D_, QKV_COLS, D_, QSC);
    transpose_k<<<dim3(D_ / 32, D_ / 32), dim3(32, 8)>>>(
        w_proj, wprojT, D_, D_, 0, 1.0f);

    // 1) QKV = Xr @ W_qkv  (rounded + perm8'd output; Q pre-scaled)
    gemm_ff<false, true, true><<<dim3(QKV_COLS / 128, M_ / 128), 256, FF_SMEM>>>(
        xr, wqkvT, nullptr, qkv, QKV_COLS, D_);

    // 2) fused flash attention -> [B,N,D] (rounded + perm8'd)
    attn_tc<<<dim3(N_ / QROWS, B_ * H_), 256, AT_SMEM>>>(qkv, att);

    // 3) OUT = ATT @ W_proj + b  (final output, standard layout)
    gemm_ff<true, false, false><<<dim3(D_ / 128, M_ / 128), 256, FF_SMEM>>>(
        att, wprojT, b_proj, out, D_, D_);
}

// round 12
// speedup vs baseline: 1.2071x; 1.0265x over previous
#include <cuda_runtime.h>
#include <math.h>
#include <stdint.h>

// ---------------------------------------------------------------------------
// Problem constants
// ---------------------------------------------------------------------------
#define B_   4
#define N_   2048
#define D_   768
#define H_   12
#define HD_  64
#define M_   (B_ * N_)             // 8192
#define QKV_COLS (3 * D_)          // 2304

// Scratch (alloc-free rule)
__device__ float g_qkv[(size_t)M_ * QKV_COLS];     // perm8 layout on d
__device__ float g_att[(size_t)M_ * D_];           // perm8 layout on d
__device__ float g_xr[(size_t)M_ * D_];            // tf32-rounded X, perm8 on k
__device__ float g_wqkvT[(size_t)QKV_COLS * D_];   // [N][K], perm8 on k
__device__ float g_wprojT[(size_t)D_ * D_];        // [N][K], perm8 on k

// perm within each 8-group: d -> (d&3)*2 + ((d>>2)&1)

// ---------------------------------------------------------------------------
// tf32 helpers (legacy mma path — harness targets sm_100 base, no tcgen05)
// ---------------------------------------------------------------------------
__device__ __forceinline__ float tff(float x) {
    float r;
    asm("{ .reg .b32 t; cvt.rna.tf32.f32 t, %1; mov.b32 %0, t; }" : "=f"(r) : "f"(x));
    return r;
}

__device__ __forceinline__ float ex2(float x) {
    float y;
    asm("ex2.approx.ftz.f32 %0, %1;" : "=f"(y) : "f"(x));
    return y;
}

__device__ __forceinline__ void mma_tf32(float* c, const uint32_t* a, const uint32_t* b) {
    asm volatile(
        "mma.sync.aligned.m16n8k8.row.col.f32.tf32.tf32.f32 "
        "{%0,%1,%2,%3}, {%4,%5,%6,%7}, {%8,%9}, {%0,%1,%2,%3};"
        : "+f"(c[0]), "+f"(c[1]), "+f"(c[2]), "+f"(c[3])
        : "r"(a[0]), "r"(a[1]), "r"(a[2]), "r"(a[3]), "r"(b[0]), "r"(b[1]));
}

__device__ __forceinline__ void cpa16(uint32_t dst, const float* src) {
    asm volatile("cp.async.ca.shared.global [%0], [%1], 16;"
                 :: "r"(dst), "l"(src) : "memory");
}
__device__ __forceinline__ void cpa_commit() {
    asm volatile("cp.async.commit_group;" ::: "memory");
}
template<int NN>
__device__ __forceinline__ void cpa_wait() {
    asm volatile("cp.async.wait_group %0;" :: "n"(NN) : "memory");
}

__device__ __forceinline__ uint32_t smem_u32(const void* p) {
    uint32_t a;
    asm("{ .reg .u64 t; cvta.to.shared.u64 t, %1; cvt.u32.u64 %0, t; }" : "=r"(a) : "l"(p));
    return a;
}

// ---------------------------------------------------------------------------
// tf32 round + perm8 interleave (X): 8 floats per thread
// ---------------------------------------------------------------------------
__global__ __launch_bounds__(256) void round_perm(
    const float* __restrict__ in, float* __restrict__ out, int n8)
{
    const int i = blockIdx.x * 256 + threadIdx.x;
    if (i < n8) {
        float4 a = ((const float4*)in)[2 * i];
        float4 b = ((const float4*)in)[2 * i + 1];
        float4 o0 = make_float4(tff(a.x), tff(b.x), tff(a.y), tff(b.y));
        float4 o1 = make_float4(tff(a.z), tff(b.z), tff(a.w), tff(b.w));
        ((float4*)out)[2 * i]     = o0;
        ((float4*)out)[2 * i + 1] = o1;
    }
}

// ---------------------------------------------------------------------------
// Weight transpose + round + perm8 on k: out[N][Kperm] = round(in[K][N]*s)
// ---------------------------------------------------------------------------
__global__ __launch_bounds__(256) void transpose_k(
    const float* __restrict__ in, float* __restrict__ out, int K, int N,
    int qrows, float qscale)
{
    __shared__ float t[32][33];
    const int kb = blockIdx.y * 32, nb = blockIdx.x * 32;
    const int x = threadIdx.x, y = threadIdx.y;
    #pragma unroll
    for (int i = 0; i < 32; i += 8)
        t[y + i][x] = in[(size_t)(kb + y + i) * N + nb + x];
    __syncthreads();
    const int k  = kb + x;
    const int kp = (k & ~7) | (((k & 3) << 1) | ((k >> 2) & 1));
    #pragma unroll
    for (int i = 0; i < 32; i += 8) {
        const int n = nb + y + i;
        const float s = (n < qrows) ? qscale : 1.0f;
        out[(size_t)n * K + kp] = tff(t[x][y + i] * s);
    }
}

// ---------------------------------------------------------------------------
// tf32 GEMM on perm8 inputs: fragment-major smem fed by cp.async 3-stage ring.
// 128x128 CTA tile, BK=32, 256 threads, 8 warps each 32x64.
// Stage = 8256 words (A 4128 + B 4128); 3 stages = 99072 B.
// ---------------------------------------------------------------------------
#define FF_STAGE 8256
#define FF_SMEM (3 * FF_STAGE * 4)

template<bool BIAS, bool ROUND, bool PERMOUT>
__global__ __launch_bounds__(256, 2) void gemm_ff(
    const float* __restrict__ A, const float* __restrict__ WT,
    const float* __restrict__ bias, float* __restrict__ C,
    int N, int K)
{
    extern __shared__ float smf[];
    const uint32_t sb4 = smem_u32(smf);

    const int tid  = threadIdx.x;
    const int lane = tid & 31;
    const int wid  = tid >> 5;
    const int g    = lane >> 2;
    const int tg   = lane & 3;
    const int wm   = wid & 3;
    const int wn   = wid >> 2;
    const int row0 = blockIdx.y * 128;
    const int col0 = blockIdx.x * 128;
    const int KT   = K / 32;

    float acc[2][8][4];
    #pragma unroll
    for (int mt = 0; mt < 2; mt++)
        #pragma unroll
        for (int nt = 0; nt < 8; nt++)
            #pragma unroll
            for (int i = 0; i < 4; i++) acc[mt][nt][i] = 0.f;

    const int lrow = tid >> 3;
    const int lkq  = tid & 7;
    const int ks0  = lkq >> 1;
    const int m0   = lkq & 1;
    const int kA   = 8 * ks0 + 4 * m0;   // perm-space float4 offset

    const float* Ap = A  + (size_t)(row0 + lrow) * K + kA;
    const float* Bp = WT + (size_t)(col0 + lrow) * K + kA;

    // per-thread smem dst word offsets (stage-relative), i = 0..3
    const int dstA0 = ks0 * 1032 + lrow * 8 + 4 * m0;   // + i*(32*8)

    #define ISSUE_G(t_) do {                                                 \
        const uint32_t sbase_ = sb4 + ((t_) % 3) * (FF_STAGE * 4);           \
        const size_t koff_ = (size_t)(t_) * 32;                             \
        _Pragma("unroll")                                                    \
        for (int i_ = 0; i_ < 4; i_++) {                                     \
            cpa16(sbase_ + (dstA0 + i_ * 256) * 4,                           \
                  Ap + (size_t)(i_ * 32) * K + koff_);                       \
            cpa16(sbase_ + (4128 + dstA0 + i_ * 256) * 4,                    \
                  Bp + (size_t)(i_ * 32) * K + koff_);                       \
        }                                                                    \
        cpa_commit();                                                        \
    } while (0)

    ISSUE_G(0);
    if (KT > 1) ISSUE_G(1);

    for (int t = 0; t < KT; t++) {
        if (t + 1 < KT) cpa_wait<1>(); else cpa_wait<0>();
        __syncthreads();

        // issue tile t+2 into stage (t+2)%3 == (t-1)%3 — its readers all
        // passed the barrier above.
        if (t + 2 < KT) ISSUE_G(t + 2);

        const float2* As2 = (const float2*)(smf + (t % 3) * FF_STAGE);
        const float2* Bs2 = As2 + 2064;   // 4128 floats

        #pragma unroll
        for (int ks = 0; ks < 4; ks++) {
            const float2* Ak = As2 + ks * 516;
            const float2* Bk = Bs2 + ks * 516;
            uint32_t af[2][4];
            #pragma unroll
            for (int mt = 0; mt < 2; mt++) {
                const int r = wm * 32 + mt * 16 + g;
                float2 v1 = Ak[r * 4 + tg];
                float2 v2 = Ak[(r + 8) * 4 + tg];
                af[mt][0] = __float_as_uint(v1.x);
                af[mt][1] = __float_as_uint(v2.x);
                af[mt][2] = __float_as_uint(v1.y);
                af[mt][3] = __float_as_uint(v2.y);
            }
            #pragma unroll
            for (int nt = 0; nt < 8; nt++) {
                const int c = wn * 64 + nt * 8 + g;
                float2 w = Bk[c * 4 + tg];
                uint32_t bf[2] = { __float_as_uint(w.x), __float_as_uint(w.y) };
                mma_tf32(acc[0][nt], af[0], bf);
                mma_tf32(acc[1][nt], af[1], bf);
            }
        }
    }
    #undef ISSUE_G

    // perm positions for output pair (2tg, 2tg+1) within its 8-group
    const int dl = 2 * tg;
    const int p0 = ((dl & 3) << 1) + (dl >> 2);
    const int p1 = (((dl + 1) & 3) << 1) + ((dl + 1) >> 2);

    #pragma unroll
    for (int mt = 0; mt < 2; mt++) {
        const int r_lo = row0 + wm * 32 + mt * 16 + g;
        const int r_hi = r_lo + 8;
        #pragma unroll
        for (int nt = 0; nt < 8; nt++) {
            const int c = col0 + wn * 64 + nt * 8 + 2 * tg;
            float2 v0 = make_float2(acc[mt][nt][0], acc[mt][nt][1]);
            float2 v1 = make_float2(acc[mt][nt][2], acc[mt][nt][3]);
            if (BIAS) {
                float2 bb = *(const float2*)&bias[c];
                v0.x += bb.x; v0.y += bb.y;
                v1.x += bb.x; v1.y += bb.y;
            }
            if (ROUND) {
                v0.x = tff(v0.x); v0.y = tff(v0.y);
                v1.x = tff(v1.x); v1.y = tff(v1.y);
            }
            if (PERMOUT) {
                const int cg = c & ~7;
                C[(size_t)r_lo * N + cg + p0] = v0.x;
                C[(size_t)r_lo * N + cg + p1] = v0.y;
                C[(size_t)r_hi * N + cg + p0] = v1.x;
                C[(size_t)r_hi * N + cg + p1] = v1.y;
            } else {
                *(float2*)&C[(size_t)r_lo * N + c] = v0;
                *(float2*)&C[(size_t)r_hi * N + c] = v1;
            }
        }
    }
}

// ---------------------------------------------------------------------------
// Flash attention (unchanged from R11 win): tf32 mma, cp.async 3-stage KV
// ring, perm8 inputs, Q fragments in regs, raw-P PV, perm8+rounded output.
// ---------------------------------------------------------------------------
#define QPL   1032
#define PS_OFF 0
#define KS_OFF 4128
#define KS_STRIDE 2304
#define VS_OFF 11040
#define VS_STRIDE 2304
#define LDK_  72
#define LDV_  72
#define QROWS 128
#define NTILES (N_ / 32)
#define AT_SMEM ((VS_OFF + 3 * VS_STRIDE) * 4)   // 71808 B

__global__ __launch_bounds__(256, 2) void attn_tc(
    const float* __restrict__ qkv, float* __restrict__ out)
{
    extern __shared__ float sm[];
    const uint32_t sb4 = smem_u32(sm);

    const int tid  = threadIdx.x;
    const int lane = tid & 31;
    const int wid  = tid >> 5;
    const int g    = lane >> 2;
    const int tg   = lane & 3;
    const int qb   = blockIdx.x;            // 0..15
    const int bh   = blockIdx.y;            // 0..47
    const int b    = bh / H_;
    const int h    = bh % H_;

    const size_t base = (size_t)b * N_ * QKV_COLS;
    const int qoff = h * HD_;
    const int koff = D_ + h * HD_;
    const int voff = 2 * D_ + h * HD_;

    const int cr0 = tid >> 4;
    const int cd  = (tid & 15) * 4;

    const float* tp = qkv + base + (size_t)cr0 * QKV_COLS;
    const size_t TILE_STEP = (size_t)32 * QKV_COLS;

    #define ISSUE_TILE(ptr_, ss_) do {                                       \
        const float* r1_ = (ptr_) + (size_t)16 * QKV_COLS;                   \
        const uint32_t kd_ = sb4 + (KS_OFF + (ss_) * KS_STRIDE) * 4;         \
        const uint32_t vd_ = sb4 + (VS_OFF + (ss_) * VS_STRIDE) * 4;         \
        cpa16(kd_ + (cr0 * LDK_ + cd) * 4,        (ptr_) + koff + cd);       \
        cpa16(kd_ + ((cr0 + 16) * LDK_ + cd) * 4, r1_ + koff + cd);          \
        cpa16(vd_ + (cr0 * LDV_ + cd) * 4,        (ptr_) + voff + cd);       \
        cpa16(vd_ + ((cr0 + 16) * LDV_ + cd) * 4, r1_ + voff + cd);          \
        cpa_commit();                                                        \
    } while (0)

    ISSUE_TILE(tp, 0);
    ISSUE_TILE(tp + TILE_STEP, 1);
    const float* tp2 = tp + 2 * TILE_STEP;

    // ---- Q fragments to registers (perm layout: pair adjacent) ----
    const int r_lo = wid * 16 + g;
    const int r_hi = r_lo + 8;
    uint32_t qf[8][4];
    {
        const float* qlo = qkv + base + (size_t)(qb * QROWS + r_lo) * QKV_COLS + qoff;
        const float* qhi = qkv + base + (size_t)(qb * QROWS + r_hi) * QKV_COLS + qoff;
        #pragma unroll
        for (int ks = 0; ks < 8; ks++) {
            float2 q0 = *(const float2*)&qlo[8 * ks + 2 * tg];
            float2 q1 = *(const float2*)&qhi[8 * ks + 2 * tg];
            qf[ks][0] = __float_as_uint(q0.x);
            qf[ks][2] = __float_as_uint(q0.y);
            qf[ks][1] = __float_as_uint(q1.x);
            qf[ks][3] = __float_as_uint(q1.y);
        }
    }

    const int dd0 = 2 * tg, dd1 = 2 * tg + 1;
    const int poff0 = (dd0 & 3) * 2 + (dd0 >> 2);
    const int poff1 = (dd1 & 3) * 2 + (dd1 >> 2);
    const int pg = ((g & 3) << 1) | (g >> 2);

    float O[8][4];
    #pragma unroll
    for (int nt = 0; nt < 8; nt++)
        #pragma unroll
        for (int i = 0; i < 4; i++) O[nt][i] = 0.f;
    float m_lo = -INFINITY, m_hi = -INFINITY, l_lo = 0.f, l_hi = 0.f;

    int ss = 0;
    for (int t = 0; t < NTILES; t++) {
        if (t == NTILES - 1) cpa_wait<0>(); else cpa_wait<1>();
        __syncthreads();

        if (t + 2 < NTILES) {
            const int ns = (ss + 2 >= 3) ? ss - 1 : ss + 2;
            ISSUE_TILE(tp2, ns);
            tp2 += TILE_STEP;
        }

        const float* Kst = sm + KS_OFF + ss * KS_STRIDE;
        const float* Vst = sm + VS_OFF + ss * VS_STRIDE;

        float s[4][4];
        #pragma unroll
        for (int nt = 0; nt < 4; nt++)
            #pragma unroll
            for (int i = 0; i < 4; i++) s[nt][i] = 0.f;

        #pragma unroll
        for (int ks = 0; ks < 8; ks++) {
            const float* Kp = Kst + 8 * ks + 2 * tg;
            #pragma unroll
            for (int nt = 0; nt < 4; nt++) {
                float2 kf = *(const float2*)&Kp[(nt * 8 + g) * LDK_];
                uint32_t bf[2] = { __float_as_uint(kf.x), __float_as_uint(kf.y) };
                mma_tf32(s[nt], qf[ks], bf);
            }
        }

        float rmx_lo = fmaxf(fmaxf(s[0][0], s[0][1]), fmaxf(s[1][0], s[1][1]));
        float rmx_hi = fmaxf(fmaxf(s[0][2], s[0][3]), fmaxf(s[1][2], s[1][3]));
        rmx_lo = fmaxf(rmx_lo, fmaxf(fmaxf(s[2][0], s[2][1]), fmaxf(s[3][0], s[3][1])));
        rmx_hi = fmaxf(rmx_hi, fmaxf(fmaxf(s[2][2], s[2][3]), fmaxf(s[3][2], s[3][3])));
        rmx_lo = fmaxf(rmx_lo, __shfl_xor_sync(0xffffffffu, rmx_lo, 1));
        rmx_lo = fmaxf(rmx_lo, __shfl_xor_sync(0xffffffffu, rmx_lo, 2));
        rmx_hi = fmaxf(rmx_hi, __shfl_xor_sync(0xffffffffu, rmx_hi, 1));
        rmx_hi = fmaxf(rmx_hi, __shfl_xor_sync(0xffffffffu, rmx_hi, 2));

        const float mn_lo = fmaxf(m_lo, rmx_lo);
        const float mn_hi = fmaxf(m_hi, rmx_hi);
        const float sc_lo = ex2(m_lo - mn_lo);
        const float sc_hi = ex2(m_hi - mn_hi);

        float rs_lo = 0.f, rs_hi = 0.f;
        #pragma unroll
        for (int nt = 0; nt < 4; nt++) {
            s[nt][0] = ex2(s[nt][0] - mn_lo);
            s[nt][1] = ex2(s[nt][1] - mn_lo);
            s[nt][2] = ex2(s[nt][2] - mn_hi);
            s[nt][3] = ex2(s[nt][3] - mn_hi);
            rs_lo += s[nt][0] + s[nt][1];
            rs_hi += s[nt][2] + s[nt][3];
        }
        rs_lo += __shfl_xor_sync(0xffffffffu, rs_lo, 1);
        rs_lo += __shfl_xor_sync(0xffffffffu, rs_lo, 2);
        rs_hi += __shfl_xor_sync(0xffffffffu, rs_hi, 1);
        rs_hi += __shfl_xor_sync(0xffffffffu, rs_hi, 2);

        l_lo = l_lo * sc_lo + rs_lo;   m_lo = mn_lo;
        l_hi = l_hi * sc_hi + rs_hi;   m_hi = mn_hi;

        #pragma unroll
        for (int nt = 0; nt < 8; nt++) {
            O[nt][0] *= sc_lo; O[nt][1] *= sc_lo;
            O[nt][2] *= sc_hi; O[nt][3] *= sc_hi;
        }

        #pragma unroll
        for (int nt = 0; nt < 4; nt++) {
            float* Pp = sm + PS_OFF + nt * QPL;
            Pp[r_lo * 8 + poff0] = s[nt][0];
            Pp[r_lo * 8 + poff1] = s[nt][1];
            Pp[r_hi * 8 + poff0] = s[nt][2];
            Pp[r_hi * 8 + poff1] = s[nt][3];
        }
        __syncwarp();

        #pragma unroll
        for (int ks = 0; ks < 4; ks++) {
            uint32_t pa[4];
            {
                const float* Pp = sm + PS_OFF + ks * QPL;
                float2 t0 = *(const float2*)&Pp[r_lo * 8 + tg * 2];
                float2 t1 = *(const float2*)&Pp[r_hi * 8 + tg * 2];
                pa[0] = __float_as_uint(t0.x); pa[2] = __float_as_uint(t0.y);
                pa[1] = __float_as_uint(t1.x); pa[3] = __float_as_uint(t1.y);
            }
            const float* Vp  = Vst + (ks * 8 + tg) * LDV_;
            const float* Vp4 = Vp + 4 * LDV_;
            #pragma unroll
            for (int nt = 0; nt < 8; nt++) {
                uint32_t bv[2] = { __float_as_uint(Vp[nt * 8 + pg]),
                                   __float_as_uint(Vp4[nt * 8 + pg]) };
                mma_tf32(O[nt], pa, bv);
            }
        }

        ss = (ss + 1 >= 3) ? 0 : ss + 1;
    }
    #undef ISSUE_TILE

    const float il_lo = 1.f / l_lo;
    const float il_hi = 1.f / l_hi;
    const int n_lo = qb * QROWS + r_lo;
    const int n_hi = n_lo + 8;
    #pragma unroll
    for (int nt = 0; nt < 8; nt++) {
        const int cg = h * HD_ + nt * 8;
        float* olo = &out[((size_t)b * N_ + n_lo) * D_ + cg];
        float* ohi = &out[((size_t)b * N_ + n_hi) * D_ + cg];
        olo[poff0] = tff(O[nt][0] * il_lo);
        olo[poff1] = tff(O[nt][1] * il_lo);
        ohi[poff0] = tff(O[nt][2] * il_hi);
        ohi[poff1] = tff(O[nt][3] * il_hi);
    }
}

// ---------------------------------------------------------------------------
// Launch
// ---------------------------------------------------------------------------
extern "C" void kernel_launch(void* const* d_in, const int* in_sizes, int n_in,
                              void* d_out, int out_size)
{
    const float* x      = (const float*)d_in[0];
    const float* w_qkv  = (const float*)d_in[1];
    const float* w_proj = (const float*)d_in[2];
    const float* b_proj = (const float*)d_in[3];
    float* out = (float*)d_out;

    float *qkv, *att, *xr, *wqkvT, *wprojT;
    cudaGetSymbolAddress((void**)&qkv, g_qkv);
    cudaGetSymbolAddress((void**)&att, g_att);
    cudaGetSymbolAddress((void**)&xr, g_xr);
    cudaGetSymbolAddress((void**)&wqkvT, g_wqkvT);
    cudaGetSymbolAddress((void**)&wprojT, g_wprojT);

    cudaFuncSetAttribute(attn_tc, cudaFuncAttributeMaxDynamicSharedMemorySize, AT_SMEM);
    cudaFuncSetAttribute((const void*)gemm_ff<false, true, true>,
                         cudaFuncAttributeMaxDynamicSharedMemorySize, FF_SMEM);
    cudaFuncSetAttribute((const void*)gemm_ff<true, false, false>,
                         cudaFuncAttributeMaxDynamicSharedMemorySize, FF_SMEM);

    const float QSC = 0.18033688011112042f;   // 0.125 * log2(e)

    // 0) pre-round+perm X; transpose+round+perm weights (Q cols pre-scaled)
    round_perm<<<(M_ * D_ / 8 + 255) / 256, 256>>>(x, xr, M_ * D_ / 8);
    transpose_k<<<dim3(QKV_COLS / 32, D_ / 32), dim3(32, 8)>>>(
        w_qkv, wqkvT, D_, QKV_COLS, D_, QSC);
    transpose_k<<<dim3(D_ / 32, D_ / 32), dim3(32, 8)>>>(
        w_proj, wprojT, D_, D_, 0, 1.0f);

    // 1) QKV = Xr @ W_qkv  (rounded + perm8'd output; Q pre-scaled)
    gemm_ff<false, true, true><<<dim3(QKV_COLS / 128, M_ / 128), 256, FF_SMEM>>>(
        xr, wqkvT, nullptr, qkv, QKV_COLS, D_);

    // 2) fused flash attention -> [B,N,D] (rounded + perm8'd)
    attn_tc<<<dim3(N_ / QROWS, B_ * H_), 256, AT_SMEM>>>(qkv, att);

    // 3) OUT = ATT @ W_proj + b  (final output, standard layout)
    gemm_ff<true, false, false><<<dim3(D_ / 128, M_ / 128), 256, FF_SMEM>>>(
        att, wprojT, b_proj, out, D_, D_);
}